// round 10
// baseline (speedup 1.0000x reference)
#include <cuda_runtime.h>
#include <math.h>

#define NN 50000
#define EE 800000
#define HH 64
#define FF 64
#define CC 10
#define KK 4
#define LL 3
#define NB_BATCH 256
#define SPAD 68

// ---------------- device scratch ----------------
__device__ float g_Z[NN * HH];
__device__ float g_h0[(size_t)NN * KK * HH];   // interleaved [n][k][64]
__device__ float g_h1[(size_t)NN * KK * HH];   // interleaved [n][k][64]
__device__ float g_AB[(size_t)KK * NN * 128];
__device__ float g_ewc[(size_t)EE * KK];       // CSR-edge-major weights [p][k]
__device__ int   g_deg[NN];
__device__ int   g_off[NN + 1];
__device__ int   g_fill[NN];
__device__ int   g_csr_src[EE];
__device__ int   g_csr_dst[EE];
__device__ int   g_csr_eid[EE];
__device__ float g_poolZ[NB_BATCH * HH];
__device__ float g_poolS[KK * NB_BATCH * HH];
__device__ int   g_cnt[NB_BATCH];

__device__ __forceinline__ void red_add_f4(float4* p, float4 v) {
    asm volatile("red.global.add.v4.f32 [%0], {%1,%2,%3,%4};"
                 :: "l"(p), "f"(v.x), "f"(v.y), "f"(v.z), "f"(v.w) : "memory");
}
__device__ __forceinline__ float sigmoidf_(float v) { return 1.0f / (1.0f + expf(-v)); }

__device__ __forceinline__ void loadW(const float* __restrict__ W, float* Ws, int tid) {
    for (int i = tid; i < 1024; i += 256) {
        float4 w = ((const float4*)W)[i];
        *((float4*)&Ws[(i >> 4) * SPAD + (i & 15) * 4]) = w;
    }
}

// 64x64x64 GEMM with packed f32x2 FMA (FFMA2): As row-major [row][k], Ws [k][col].
__device__ __forceinline__ void gemm64x2(const float* As, const float* Ws,
                                         unsigned long long acc2[4][2], int tx, int ty) {
    #pragma unroll
    for (int i = 0; i < 4; i++)
        #pragma unroll
        for (int j = 0; j < 2; j++) acc2[i][j] = 0ULL;
    #pragma unroll
    for (int kk = 0; kk < 64; kk += 4) {
        unsigned long long bp[4][2];
        #pragma unroll
        for (int s = 0; s < 4; s++) {
            ulonglong2 b2 = *((const ulonglong2*)&Ws[(kk + s) * SPAD + tx * 4]);
            bp[s][0] = b2.x; bp[s][1] = b2.y;
        }
        #pragma unroll
        for (int i = 0; i < 4; i++) {
            float4 a4 = *((const float4*)&As[(ty * 4 + i) * SPAD + kk]);
            float av[4] = {a4.x, a4.y, a4.z, a4.w};
            #pragma unroll
            for (int s = 0; s < 4; s++) {
                unsigned long long ad;
                asm("mov.b64 %0, {%1, %1};" : "=l"(ad) : "f"(av[s]));
                asm("fma.rn.f32x2 %0, %1, %2, %0;"
                    : "+l"(acc2[i][0]) : "l"(ad), "l"(bp[s][0]));
                asm("fma.rn.f32x2 %0, %1, %2, %0;"
                    : "+l"(acc2[i][1]) : "l"(ad), "l"(bp[s][1]));
            }
        }
    }
}

__device__ __forceinline__ void unpack_acc(const unsigned long long acc2[4][2],
                                           float acc[4][4]) {
    #pragma unroll
    for (int i = 0; i < 4; i++)
        #pragma unroll
        for (int j = 0; j < 2; j++) {
            float lo, hi;
            asm("mov.b64 {%0, %1}, %2;" : "=f"(lo), "=f"(hi) : "l"(acc2[i][j]));
            acc[i][2 * j] = lo; acc[i][2 * j + 1] = hi;
        }
}

__device__ __forceinline__ void gemm64(const float* As, const float* Ws,
                                       float acc[4][4], int tx, int ty) {
    unsigned long long a2[4][2];
    gemm64x2(As, Ws, a2, tx, ty);
    unpack_acc(a2, acc);
}

// ---------------- init: zero all accumulators in one launch ----------------
__global__ __launch_bounds__(256) void init_kernel() {
    int i = blockIdx.x * 256 + threadIdx.x;
    if (i < NN) { g_deg[i] = 0; g_fill[i] = 0; }
    if (i < NB_BATCH) g_cnt[i] = 0;
    if (i < NB_BATCH * HH) g_poolZ[i] = 0.f;
    if (i < KK * NB_BATCH * HH) g_poolS[i] = 0.f;
}

// ---------------- CSR build: histogram + batch counts in one kernel ----------------
__global__ __launch_bounds__(256) void histcnt_kernel(const int* __restrict__ dst,
                                                      const int* __restrict__ batch) {
    int e = blockIdx.x * 256 + threadIdx.x;
    if (e < EE) atomicAdd(&g_deg[dst[e]], 1);
    if (e < NN) atomicAdd(&g_cnt[batch[e]], 1);
}

__global__ __launch_bounds__(1024) void scan_kernel() {
    __shared__ int wsum[32];
    __shared__ int carry_s;
    int tid = threadIdx.x, lane = tid & 31, wid = tid >> 5;
    if (tid == 0) carry_s = 0;
    __syncthreads();
    for (int base = 0; base < NN; base += 1024) {
        int v = (base + tid < NN) ? g_deg[base + tid] : 0;
        int inc = v;
        #pragma unroll
        for (int off = 1; off < 32; off <<= 1) {
            int t = __shfl_up_sync(0xffffffffu, inc, off);
            if (lane >= off) inc += t;
        }
        if (lane == 31) wsum[wid] = inc;
        __syncthreads();
        if (wid == 0) {
            int s = wsum[lane];
            #pragma unroll
            for (int off = 1; off < 32; off <<= 1) {
                int t = __shfl_up_sync(0xffffffffu, s, off);
                if (lane >= off) s += t;
            }
            wsum[lane] = s;
        }
        __syncthreads();
        int wpre = wid ? wsum[wid - 1] : 0;
        int excl = carry_s + wpre + inc - v;
        if (base + tid < NN) g_off[base + tid] = excl;
        __syncthreads();
        if (tid == 0) carry_s += wsum[31];
        __syncthreads();
    }
    if (threadIdx.x == 0) g_off[NN] = carry_s;
}

__global__ __launch_bounds__(256) void fill_kernel(const int* __restrict__ src,
                                                   const int* __restrict__ dst) {
    int e = blockIdx.x * 256 + threadIdx.x;
    if (e < EE) {
        int d = dst[e];
        int pos = g_off[d] + atomicAdd(&g_fill[d], 1);
        g_csr_src[pos] = src[e];
        g_csr_dst[pos] = d;
        g_csr_eid[pos] = e;
    }
}

// ---------------- encoder GIN layer ----------------
__global__ __launch_bounds__(256, 5) void ginenc_kernel(
    const float* __restrict__ hin, float* __restrict__ hout,
    const float* __restrict__ eps_ptr, int lidx,
    const float* __restrict__ W1, const float* __restrict__ b1,
    const float* __restrict__ W2, const float* __restrict__ b2,
    float* __restrict__ pool, const int* __restrict__ batch)
{
    __shared__ __align__(16) float As[64 * SPAD];
    __shared__ __align__(16) float Ws[64 * SPAD];
    __shared__ float bsh[64], bsh2[64];
    int tid = threadIdx.x;
    int r0 = blockIdx.x * 64;
    float epsv = 1.0f + eps_ptr[lidx];
    int part = tid & 15, grp = tid >> 4;

    #pragma unroll
    for (int rr = 0; rr < 4; rr++) {
        int row = rr * 16 + grp;
        int gr = r0 + row;
        float4 a = make_float4(0.f, 0.f, 0.f, 0.f);
        if (gr < NN) {
            float4 h = ((const float4*)(hin + (size_t)gr * HH))[part];
            a.x = epsv * h.x; a.y = epsv * h.y; a.z = epsv * h.z; a.w = epsv * h.w;
            int beg = g_off[gr], end = g_off[gr + 1];
            int p = beg;
            for (; p + 1 < end; p += 2) {
                int s0 = g_csr_src[p], s1 = g_csr_src[p + 1];
                float4 v0 = ((const float4*)(hin + (size_t)s0 * HH))[part];
                float4 v1 = ((const float4*)(hin + (size_t)s1 * HH))[part];
                a.x += v0.x + v1.x; a.y += v0.y + v1.y;
                a.z += v0.z + v1.z; a.w += v0.w + v1.w;
            }
            if (p < end) {
                int s0 = g_csr_src[p];
                float4 v0 = ((const float4*)(hin + (size_t)s0 * HH))[part];
                a.x += v0.x; a.y += v0.y; a.z += v0.z; a.w += v0.w;
            }
        }
        *((float4*)&As[row * SPAD + part * 4]) = a;
    }

    loadW(W1, Ws, tid);
    if (tid < 64) { bsh[tid] = b1[tid]; bsh2[tid] = b2[tid]; }
    __syncthreads();

    int tx = tid & 15, ty = tid >> 4;
    float acc[4][4];
    gemm64(As, Ws, acc, tx, ty);
    __syncthreads();
    #pragma unroll
    for (int i = 0; i < 4; i++) {
        float4 h;
        h.x = fmaxf(acc[i][0] + bsh[tx*4+0], 0.f);
        h.y = fmaxf(acc[i][1] + bsh[tx*4+1], 0.f);
        h.z = fmaxf(acc[i][2] + bsh[tx*4+2], 0.f);
        h.w = fmaxf(acc[i][3] + bsh[tx*4+3], 0.f);
        *((float4*)&As[(ty * 4 + i) * SPAD + tx * 4]) = h;
    }
    loadW(W2, Ws, tid);
    __syncthreads();
    gemm64(As, Ws, acc, tx, ty);
    #pragma unroll
    for (int i = 0; i < 4; i++) {
        int go = r0 + ty * 4 + i;
        if (go < NN) {
            float4 o;
            o.x = fmaxf(acc[i][0] + bsh2[tx*4+0], 0.f);
            o.y = fmaxf(acc[i][1] + bsh2[tx*4+1], 0.f);
            o.z = fmaxf(acc[i][2] + bsh2[tx*4+2], 0.f);
            o.w = fmaxf(acc[i][3] + bsh2[tx*4+3], 0.f);
            *((float4*)(hout + (size_t)go * HH + tx * 4)) = o;
            if (pool) {
                int b = batch[go];
                red_add_f4((float4*)(pool + (size_t)b * HH + tx * 4), o);
            }
        }
    }
}

// ---------------- classifier GIN layer, all K experts, interleaved [n][k][64] ----------
__global__ __launch_bounds__(256, 5) void gincl_kernel(
    const float* __restrict__ hin, float* __restrict__ hout,
    const float* __restrict__ eps_ptr, int lidx,
    const float* __restrict__ W1, const float* __restrict__ b1,
    const float* __restrict__ W2, const float* __restrict__ b2,
    float* __restrict__ pool, const int* __restrict__ batch)
{
    __shared__ __align__(16) float As[64 * SPAD];
    __shared__ __align__(16) float Ws[64 * SPAD];
    __shared__ float bsh[64], bsh2[64];
    int tid = threadIdx.x;
    int n0 = blockIdx.x * 16;
    float epsv = 1.0f + eps_ptr[lidx];
    int part = tid & 15, grp = tid >> 4;

    {
        int gr = n0 + grp;
        const float4* hbase = (const float4*)(hin + (size_t)gr * KK * HH);
        float4 a[4];
        #pragma unroll
        for (int k = 0; k < 4; k++) {
            float4 h = hbase[k * 16 + part];
            a[k].x = epsv * h.x; a[k].y = epsv * h.y;
            a[k].z = epsv * h.z; a[k].w = epsv * h.w;
        }
        int beg = g_off[gr], end = g_off[gr + 1];
        int p = beg;
        int s_next = (p < end) ? g_csr_src[p] : 0;
        for (; p < end; p++) {
            int s = s_next;
            if (p + 1 < end) s_next = g_csr_src[p + 1];
            float4 w4 = *((const float4*)(g_ewc + (size_t)p * 4));
            const float4* vb = (const float4*)(hin + (size_t)s * KK * HH);
            float4 v0 = vb[0 * 16 + part];
            float4 v1 = vb[1 * 16 + part];
            float4 v2 = vb[2 * 16 + part];
            float4 v3 = vb[3 * 16 + part];
            a[0].x = fmaf(w4.x, v0.x, a[0].x); a[0].y = fmaf(w4.x, v0.y, a[0].y);
            a[0].z = fmaf(w4.x, v0.z, a[0].z); a[0].w = fmaf(w4.x, v0.w, a[0].w);
            a[1].x = fmaf(w4.y, v1.x, a[1].x); a[1].y = fmaf(w4.y, v1.y, a[1].y);
            a[1].z = fmaf(w4.y, v1.z, a[1].z); a[1].w = fmaf(w4.y, v1.w, a[1].w);
            a[2].x = fmaf(w4.z, v2.x, a[2].x); a[2].y = fmaf(w4.z, v2.y, a[2].y);
            a[2].z = fmaf(w4.z, v2.z, a[2].z); a[2].w = fmaf(w4.z, v2.w, a[2].w);
            a[3].x = fmaf(w4.w, v3.x, a[3].x); a[3].y = fmaf(w4.w, v3.y, a[3].y);
            a[3].z = fmaf(w4.w, v3.z, a[3].z); a[3].w = fmaf(w4.w, v3.w, a[3].w);
        }
        #pragma unroll
        for (int k = 0; k < 4; k++)
            *((float4*)&As[(grp * 4 + k) * SPAD + part * 4]) = a[k];
    }

    loadW(W1, Ws, tid);
    if (tid < 64) { bsh[tid] = b1[tid]; bsh2[tid] = b2[tid]; }
    __syncthreads();

    int tx = tid & 15, ty = tid >> 4;
    float acc[4][4];
    gemm64(As, Ws, acc, tx, ty);
    __syncthreads();
    #pragma unroll
    for (int i = 0; i < 4; i++) {
        float4 h;
        h.x = fmaxf(acc[i][0] + bsh[tx*4+0], 0.f);
        h.y = fmaxf(acc[i][1] + bsh[tx*4+1], 0.f);
        h.z = fmaxf(acc[i][2] + bsh[tx*4+2], 0.f);
        h.w = fmaxf(acc[i][3] + bsh[tx*4+3], 0.f);
        *((float4*)&As[(ty * 4 + i) * SPAD + tx * 4]) = h;
    }
    loadW(W2, Ws, tid);
    __syncthreads();
    gemm64(As, Ws, acc, tx, ty);
    #pragma unroll
    for (int i = 0; i < 4; i++) {
        int row = ty * 4 + i;
        int gn = n0 + (row >> 2);
        int ke = row & 3;
        float4 o;
        o.x = fmaxf(acc[i][0] + bsh2[tx*4+0], 0.f);
        o.y = fmaxf(acc[i][1] + bsh2[tx*4+1], 0.f);
        o.z = fmaxf(acc[i][2] + bsh2[tx*4+2], 0.f);
        o.w = fmaxf(acc[i][3] + bsh2[tx*4+3], 0.f);
        *((float4*)(hout + ((size_t)gn * KK + ke) * HH + tx * 4)) = o;
        if (pool) {
            int b = batch[gn];
            red_add_f4((float4*)(pool + ((size_t)ke * NB_BATCH + b) * HH + tx * 4), o);
        }
    }
}

// ---------------- fused mask kernel: nm + AB precompute + fm + masked_x ----------------
__global__ __launch_bounds__(256, 5) void mask_kernel(
    const float* __restrict__ Z, const float* __restrict__ x,
    const float* __restrict__ nmW1, const float* __restrict__ nmb1,
    const float* __restrict__ nmW2, const float* __restrict__ nmb2,
    const float* __restrict__ emW1,
    const float* __restrict__ fmW1, const float* __restrict__ fmb1,
    const float* __restrict__ fmW2, const float* __restrict__ fmb2,
    float* __restrict__ out_nm, float* __restrict__ out_fm)
{
    __shared__ __align__(16) float As[64 * SPAD];
    __shared__ __align__(16) float Ws[64 * SPAD];
    __shared__ float bsh[64], bsh2[64], w2s[64], nmv[64];
    int tid = threadIdx.x, r0 = blockIdx.x * 64;
    int k = blockIdx.y;
    const float* nmW1k = nmW1 + (size_t)k * 4096;
    const float* nmb1k = nmb1 + (size_t)k * 64;
    const float* nmW2k = nmW2 + (size_t)k * 64;
    const float* emW1k = emW1 + (size_t)k * 8192;
    const float* fmW1k = fmW1 + (size_t)k * 4096;
    const float* fmb1k = fmb1 + (size_t)k * 64;
    const float* fmW2k = fmW2 + (size_t)k * 4096;
    const float* fmb2k = fmb2 + (size_t)k * 64;
    float* ABk = g_AB + (size_t)k * NN * 128;

    {
        int row = tid >> 2, p0 = (tid & 3) * 4, gr = r0 + row;
        #pragma unroll
        for (int q = 0; q < 4; q++) {
            float4 v = make_float4(0.f, 0.f, 0.f, 0.f);
            if (gr < NN) v = ((const float4*)(Z + (size_t)gr * HH))[p0 + q];
            *((float4*)&As[row * SPAD + (p0 + q) * 4]) = v;
        }
    }
    int tx = tid & 15, ty = tid >> 4;
    float acc[4][4];

    // ---- node mask ----
    loadW(nmW1k, Ws, tid);
    if (tid < 64) { bsh[tid] = nmb1k[tid]; w2s[tid] = nmW2k[tid]; }
    __syncthreads();
    gemm64(As, Ws, acc, tx, ty);
    float b2v = nmb2[k];
    #pragma unroll
    for (int i = 0; i < 4; i++) {
        float p = 0.f;
        #pragma unroll
        for (int j = 0; j < 4; j++)
            p += fmaxf(acc[i][j] + bsh[tx*4+j], 0.f) * w2s[tx*4+j];
        #pragma unroll
        for (int off = 8; off > 0; off >>= 1)
            p += __shfl_down_sync(0xffffffffu, p, off, 16);
        if (tx == 0) {
            float sg = sigmoidf_(p + b2v);
            nmv[ty * 4 + i] = sg;
            int gr = r0 + ty * 4 + i;
            if (gr < NN) out_nm[(size_t)gr * KK + k] = sg;
        }
    }

    // ---- AB precompute ----
    #pragma unroll
    for (int half = 0; half < 2; half++) {
        __syncthreads();
        loadW(emW1k + half * 4096, Ws, tid);
        __syncthreads();
        gemm64(As, Ws, acc, tx, ty);
        #pragma unroll
        for (int i = 0; i < 4; i++) {
            int gr = r0 + ty * 4 + i;
            if (gr < NN) {
                float4 o = make_float4(acc[i][0], acc[i][1], acc[i][2], acc[i][3]);
                *((float4*)(ABk + (size_t)gr * 128 + half * 64 + tx * 4)) = o;
            }
        }
    }

    // ---- feature mask + masked_x (interleaved h0 store) ----
    __syncthreads();
    loadW(fmW1k, Ws, tid);
    if (tid < 64) { bsh[tid] = fmb1k[tid]; bsh2[tid] = fmb2k[tid]; }
    __syncthreads();
    gemm64(As, Ws, acc, tx, ty);
    __syncthreads();
    #pragma unroll
    for (int i = 0; i < 4; i++) {
        float4 h;
        h.x = fmaxf(acc[i][0] + bsh[tx*4+0], 0.f);
        h.y = fmaxf(acc[i][1] + bsh[tx*4+1], 0.f);
        h.z = fmaxf(acc[i][2] + bsh[tx*4+2], 0.f);
        h.w = fmaxf(acc[i][3] + bsh[tx*4+3], 0.f);
        *((float4*)&As[(ty * 4 + i) * SPAD + tx * 4]) = h;
    }
    loadW(fmW2k, Ws, tid);
    __syncthreads();
    gemm64(As, Ws, acc, tx, ty);
    #pragma unroll
    for (int i = 0; i < 4; i++) {
        int gr = r0 + ty * 4 + i;
        if (gr < NN) {
            float nmu = nmv[ty * 4 + i];
            float4 xr = *((const float4*)(x + (size_t)gr * FF + tx * 4));
            float4 sg;
            sg.x = sigmoidf_(acc[i][0] + bsh2[tx*4+0]);
            sg.y = sigmoidf_(acc[i][1] + bsh2[tx*4+1]);
            sg.z = sigmoidf_(acc[i][2] + bsh2[tx*4+2]);
            sg.w = sigmoidf_(acc[i][3] + bsh2[tx*4+3]);
            *((float4*)(out_fm + ((size_t)gr * KK + k) * FF + tx * 4)) = sg;
            float4 m = make_float4(xr.x * nmu * sg.x, xr.y * nmu * sg.y,
                                   xr.z * nmu * sg.z, xr.w * nmu * sg.w);
            *((float4*)(g_h0 + ((size_t)gr * KK + k) * HH + tx * 4)) = m;
        }
    }
}

// ---------------- edge mask: 16 lanes/edge, iterating CSR positions ----------
__global__ __launch_bounds__(256) void edge_mask_kernel(
    const float* __restrict__ emb1, const float* __restrict__ emW2,
    const float* __restrict__ emb2, float* __restrict__ out_em)
{
    __shared__ __align__(16) float b1s[64];
    __shared__ __align__(16) float w2s[64];
    int tid = threadIdx.x;
    int k = blockIdx.y;
    if (tid < 64) { b1s[tid] = emb1[k * 64 + tid]; w2s[tid] = emW2[k * 64 + tid]; }
    __syncthreads();
    const float* ABk = g_AB + (size_t)k * NN * 128;
    int idx = blockIdx.x * 256 + tid;
    int p = idx >> 4, lane = idx & 15;
    int s = g_csr_src[p], d = g_csr_dst[p];
    float4 a  = *((const float4*)(ABk + (size_t)s * 128) + lane);
    float4 bb = *((const float4*)(ABk + (size_t)d * 128 + 64) + lane);
    float4 bi = ((const float4*)b1s)[lane];
    float4 w  = ((const float4*)w2s)[lane];
    float pp = fmaxf(a.x + bb.x + bi.x, 0.f) * w.x
             + fmaxf(a.y + bb.y + bi.y, 0.f) * w.y
             + fmaxf(a.z + bb.z + bi.z, 0.f) * w.z
             + fmaxf(a.w + bb.w + bi.w, 0.f) * w.w;
    #pragma unroll
    for (int off = 8; off > 0; off >>= 1)
        pp += __shfl_down_sync(0xffffffffu, pp, off, 16);
    if (lane == 0) {
        float sg = sigmoidf_(pp + emb2[k]);
        g_ewc[(size_t)p * KK + k] = sg;
        out_em[(size_t)g_csr_eid[p] * KK + k] = sg;
    }
}

// ---------------- finalize ----------------
__global__ __launch_bounds__(64) void finalize_kernel(
    const float* __restrict__ clfW, const float* __restrict__ clfb,
    float* __restrict__ out_logits, float* __restrict__ out_hstab,
    float* __restrict__ out_horig)
{
    int b = blockIdx.x, t = threadIdx.x;
    __shared__ float hs[64];
    float inv = 1.0f / fmaxf((float)g_cnt[b], 1.0f);
    out_horig[b * HH + t] = g_poolZ[b * HH + t] * inv;
    for (int k = 0; k < KK; k++) {
        float v = g_poolS[((size_t)k * NB_BATCH + b) * HH + t] * inv;
        out_hstab[((size_t)b * KK + k) * HH + t] = v;
        hs[t] = v;
        __syncthreads();
        if (t < CC) {
            float sacc = clfb[k * CC + t];
            #pragma unroll 8
            for (int h2 = 0; h2 < HH; h2++)
                sacc += hs[h2] * clfW[((size_t)k * HH + h2) * CC + t];
            out_logits[((size_t)b * KK + k) * CC + t] = sacc;
        }
        __syncthreads();
    }
}

// ---------------- host launch ----------------
extern "C" void kernel_launch(void* const* d_in, const int* in_sizes, int n_in,
                              void* d_out, int out_size)
{
    const float* x     = (const float*)d_in[0];
    const int*   ei    = (const int*)d_in[1];
    const int*   batch = (const int*)d_in[2];
    const float* ceW1  = (const float*)d_in[3];
    const float* ceb1  = (const float*)d_in[4];
    const float* ceW2  = (const float*)d_in[5];
    const float* ceb2  = (const float*)d_in[6];
    const float* ceeps = (const float*)d_in[7];
    const float* clW1  = (const float*)d_in[8];
    const float* clb1  = (const float*)d_in[9];
    const float* clW2  = (const float*)d_in[10];
    const float* clb2  = (const float*)d_in[11];
    const float* cleps = (const float*)d_in[12];
    const float* nmW1  = (const float*)d_in[13];
    const float* nmb1  = (const float*)d_in[14];
    const float* nmW2  = (const float*)d_in[15];
    const float* nmb2  = (const float*)d_in[16];
    const float* emW1  = (const float*)d_in[17];
    const float* emb1  = (const float*)d_in[18];
    const float* emW2  = (const float*)d_in[19];
    const float* emb2  = (const float*)d_in[20];
    const float* fmW1  = (const float*)d_in[21];
    const float* fmb1  = (const float*)d_in[22];
    const float* fmW2  = (const float*)d_in[23];
    const float* fmb2  = (const float*)d_in[24];
    const float* clfW  = (const float*)d_in[25];
    const float* clfb  = (const float*)d_in[26];

    const int* src = ei;
    const int* dst = ei + EE;

    float* Z_p;     cudaGetSymbolAddress((void**)&Z_p, g_Z);
    float* h0_p;    cudaGetSymbolAddress((void**)&h0_p, g_h0);
    float* h1_p;    cudaGetSymbolAddress((void**)&h1_p, g_h1);
    float* poolZ_p; cudaGetSymbolAddress((void**)&poolZ_p, g_poolZ);
    float* poolS_p; cudaGetSymbolAddress((void**)&poolS_p, g_poolS);

    float* out        = (float*)d_out;
    float* out_logits = out;
    float* out_hstab  = out_logits + NB_BATCH * KK * CC;
    float* out_horig  = out_hstab + NB_BATCH * KK * HH;
    float* out_nm     = out_horig + NB_BATCH * HH;
    float* out_em     = out_nm + (size_t)NN * KK;
    float* out_fm     = out_em + (size_t)EE * KK;

    const int GB = (NN + 63) / 64;          // 782
    const int GC = NN / 16;                 // 3125
    const int EG = (EE + 255) / 256;        // 3125
    const int EDGE_GRID = (EE * 16) / 256;  // 50000
    const int IG = (KK * NB_BATCH * HH + 255) / 256;

    // ---- CSR build + init ----
    init_kernel<<<IG, 256>>>();
    histcnt_kernel<<<EG, 256>>>(dst, batch);
    scan_kernel<<<1, 1024>>>();
    fill_kernel<<<EG, 256>>>(src, dst);

    // ---- causal encoder GIN (3 layers); layer 3 fuses Z pooling ----
    ginenc_kernel<<<GB, 256>>>(x, h1_p, ceeps, 0, ceW1, ceb1, ceW2, ceb2, nullptr, nullptr);
    ginenc_kernel<<<GB, 256>>>(h1_p, h0_p, ceeps, 1, ceW1 + 4096, ceb1 + 64,
                               ceW2 + 4096, ceb2 + 64, nullptr, nullptr);
    ginenc_kernel<<<GB, 256>>>(h0_p, Z_p, ceeps, 2, ceW1 + 8192, ceb1 + 128,
                               ceW2 + 8192, ceb2 + 128, poolZ_p, batch);

    // ---- masks (writes interleaved g_h0) ----
    mask_kernel<<<dim3(GB, KK), 256>>>(Z_p, x, nmW1, nmb1, nmW2, nmb2,
                                       emW1, fmW1, fmb1, fmW2, fmb2,
                                       out_nm, out_fm);
    edge_mask_kernel<<<dim3(EDGE_GRID, KK), 256>>>(emb1, emW2, emb2, out_em);

    // ---- classifier GIN (3 layers, all K); layer 3 fuses pooling ----
    gincl_kernel<<<GC, 256>>>(h0_p, h1_p, cleps, 0, clW1, clb1, clW2, clb2,
                              nullptr, nullptr);
    gincl_kernel<<<GC, 256>>>(h1_p, h0_p, cleps, 1, clW1 + 4096, clb1 + 64,
                              clW2 + 4096, clb2 + 64, nullptr, nullptr);
    gincl_kernel<<<GC, 256>>>(h0_p, h1_p, cleps, 2, clW1 + 8192, clb1 + 128,
                              clW2 + 8192, clb2 + 128, poolS_p, batch);

    // ---- finalize ----
    finalize_kernel<<<NB_BATCH, 64>>>(clfW, clfb, out_logits, out_hstab, out_horig);
}

// round 11
// speedup vs baseline: 1.0607x; 1.0607x over previous
#include <cuda_runtime.h>
#include <math.h>
#include <stdint.h>

#define NN 50000
#define EE 800000
#define HH 64
#define FF 64
#define CC 10
#define KK 4
#define LL 3
#define NB_BATCH 256
#define SPAD 68

// ---------------- device scratch ----------------
__device__ float g_Z[NN * HH];
__device__ float g_h0[(size_t)NN * KK * HH];   // interleaved [n][k][64]
__device__ float g_h1[(size_t)NN * KK * HH];   // interleaved [n][k][64]
__device__ float g_AB[(size_t)KK * NN * 128];
__device__ float g_ewc[(size_t)EE * KK];       // CSR-edge-major weights [p][k]
__device__ int   g_deg[NN];
__device__ int   g_off[NN + 1];
__device__ int   g_fill[NN];
__device__ int   g_csr_src[EE];
__device__ int   g_csr_dst[EE];
__device__ int   g_csr_eid[EE];
__device__ float g_poolZ[NB_BATCH * HH];
__device__ float g_poolS[KK * NB_BATCH * HH];
__device__ int   g_cnt[NB_BATCH];

__device__ __forceinline__ void red_add_f4(float4* p, float4 v) {
    asm volatile("red.global.add.v4.f32 [%0], {%1,%2,%3,%4};"
                 :: "l"(p), "f"(v.x), "f"(v.y), "f"(v.z), "f"(v.w) : "memory");
}
__device__ __forceinline__ float sigmoidf_(float v) { return 1.0f / (1.0f + expf(-v)); }

__device__ __forceinline__ void loadW(const float* __restrict__ W, float* Ws, int tid) {
    for (int i = tid; i < 1024; i += 256) {
        float4 w = ((const float4*)W)[i];
        *((float4*)&Ws[(i >> 4) * SPAD + (i & 15) * 4]) = w;
    }
}

__device__ __forceinline__ uint32_t tf32_rna(float a) {
    uint32_t h; asm("cvt.rna.tf32.f32 %0, %1;" : "=r"(h) : "f"(a)); return h;
}

#define MMA_TF32(c, A0, A1, A2, A3, B0, B1) \
    asm("mma.sync.aligned.m16n8k8.row.col.f32.tf32.tf32.f32 " \
        "{%0,%1,%2,%3}, {%4,%5,%6,%7}, {%8,%9}, {%0,%1,%2,%3};" \
        : "+f"((c)[0]), "+f"((c)[1]), "+f"((c)[2]), "+f"((c)[3]) \
        : "r"(A0), "r"(A1), "r"(A2), "r"(A3), "r"(B0), "r"(B1))

// 64x64x64 GEMM via tf32 tensor MMA with hi/lo split (~fp32 accuracy).
// As row-major [row][k] (SPAD stride), Ws [k][col]. Result staged in Cs; after an
// internal __syncthreads each thread loads acc[4][4] in the legacy (tx,ty) layout.
// ALL 256 threads must call this (contains __syncthreads).
__device__ __forceinline__ void gemm64(const float* As, const float* Ws, float* Cs,
                                       float acc[4][4], int tid, int tx, int ty) {
    int lane = tid & 31, warp = tid >> 5;
    int mband = (warp & 3) * 16;      // 16-row band
    int nhalf = (warp >> 2) * 32;     // 32-col half
    int lr = lane >> 2, lc = lane & 3;

    float c[4][4];
    #pragma unroll
    for (int nt = 0; nt < 4; nt++)
        #pragma unroll
        for (int q = 0; q < 4; q++) c[nt][q] = 0.f;

    #pragma unroll
    for (int ks = 0; ks < 8; ks++) {
        int k0 = ks * 8;
        float a0 = As[(mband + lr) * SPAD + k0 + lc];
        float a1 = As[(mband + 8 + lr) * SPAD + k0 + lc];
        float a2 = As[(mband + lr) * SPAD + k0 + 4 + lc];
        float a3 = As[(mband + 8 + lr) * SPAD + k0 + 4 + lc];
        uint32_t ah0 = tf32_rna(a0), ah1 = tf32_rna(a1);
        uint32_t ah2 = tf32_rna(a2), ah3 = tf32_rna(a3);
        uint32_t al0 = tf32_rna(a0 - __uint_as_float(ah0));
        uint32_t al1 = tf32_rna(a1 - __uint_as_float(ah1));
        uint32_t al2 = tf32_rna(a2 - __uint_as_float(ah2));
        uint32_t al3 = tf32_rna(a3 - __uint_as_float(ah3));
        #pragma unroll
        for (int nt = 0; nt < 4; nt++) {
            int n0 = nhalf + nt * 8;
            float b0 = Ws[(k0 + lc) * SPAD + n0 + lr];
            float b1 = Ws[(k0 + 4 + lc) * SPAD + n0 + lr];
            uint32_t bh0 = tf32_rna(b0), bh1 = tf32_rna(b1);
            uint32_t bl0 = tf32_rna(b0 - __uint_as_float(bh0));
            uint32_t bl1 = tf32_rna(b1 - __uint_as_float(bh1));
            MMA_TF32(c[nt], ah0, ah1, ah2, ah3, bh0, bh1);
            MMA_TF32(c[nt], al0, al1, al2, al3, bh0, bh1);
            MMA_TF32(c[nt], ah0, ah1, ah2, ah3, bl0, bl1);
        }
    }
    #pragma unroll
    for (int nt = 0; nt < 4; nt++) {
        int col = nhalf + nt * 8 + lc * 2;
        *((float2*)&Cs[(mband + lr) * SPAD + col])     = make_float2(c[nt][0], c[nt][1]);
        *((float2*)&Cs[(mband + 8 + lr) * SPAD + col]) = make_float2(c[nt][2], c[nt][3]);
    }
    __syncthreads();
    #pragma unroll
    for (int i = 0; i < 4; i++) {
        float4 v = *((const float4*)&Cs[(ty * 4 + i) * SPAD + tx * 4]);
        acc[i][0] = v.x; acc[i][1] = v.y; acc[i][2] = v.z; acc[i][3] = v.w;
    }
}

// ---------------- init: zero all accumulators in one launch ----------------
__global__ __launch_bounds__(256) void init_kernel() {
    int i = blockIdx.x * 256 + threadIdx.x;
    if (i < NN) { g_deg[i] = 0; g_fill[i] = 0; }
    if (i < NB_BATCH) g_cnt[i] = 0;
    if (i < NB_BATCH * HH) g_poolZ[i] = 0.f;
    if (i < KK * NB_BATCH * HH) g_poolS[i] = 0.f;
}

// ---------------- CSR build: histogram + batch counts in one kernel ----------------
__global__ __launch_bounds__(256) void histcnt_kernel(const int* __restrict__ dst,
                                                      const int* __restrict__ batch) {
    int e = blockIdx.x * 256 + threadIdx.x;
    if (e < EE) atomicAdd(&g_deg[dst[e]], 1);
    if (e < NN) atomicAdd(&g_cnt[batch[e]], 1);
}

__global__ __launch_bounds__(1024) void scan_kernel() {
    __shared__ int wsum[32];
    __shared__ int carry_s;
    int tid = threadIdx.x, lane = tid & 31, wid = tid >> 5;
    if (tid == 0) carry_s = 0;
    __syncthreads();
    for (int base = 0; base < NN; base += 1024) {
        int v = (base + tid < NN) ? g_deg[base + tid] : 0;
        int inc = v;
        #pragma unroll
        for (int off = 1; off < 32; off <<= 1) {
            int t = __shfl_up_sync(0xffffffffu, inc, off);
            if (lane >= off) inc += t;
        }
        if (lane == 31) wsum[wid] = inc;
        __syncthreads();
        if (wid == 0) {
            int s = wsum[lane];
            #pragma unroll
            for (int off = 1; off < 32; off <<= 1) {
                int t = __shfl_up_sync(0xffffffffu, s, off);
                if (lane >= off) s += t;
            }
            wsum[lane] = s;
        }
        __syncthreads();
        int wpre = wid ? wsum[wid - 1] : 0;
        int excl = carry_s + wpre + inc - v;
        if (base + tid < NN) g_off[base + tid] = excl;
        __syncthreads();
        if (tid == 0) carry_s += wsum[31];
        __syncthreads();
    }
    if (threadIdx.x == 0) g_off[NN] = carry_s;
}

__global__ __launch_bounds__(256) void fill_kernel(const int* __restrict__ src,
                                                   const int* __restrict__ dst) {
    int e = blockIdx.x * 256 + threadIdx.x;
    if (e < EE) {
        int d = dst[e];
        int pos = g_off[d] + atomicAdd(&g_fill[d], 1);
        g_csr_src[pos] = src[e];
        g_csr_dst[pos] = d;
        g_csr_eid[pos] = e;
    }
}

// ---------------- encoder GIN layer ----------------
__global__ __launch_bounds__(256) void ginenc_kernel(
    const float* __restrict__ hin, float* __restrict__ hout,
    const float* __restrict__ eps_ptr, int lidx,
    const float* __restrict__ W1, const float* __restrict__ b1,
    const float* __restrict__ W2, const float* __restrict__ b2,
    float* __restrict__ pool, const int* __restrict__ batch)
{
    __shared__ __align__(16) float As[64 * SPAD];
    __shared__ __align__(16) float Ws[64 * SPAD];
    __shared__ __align__(16) float Cs[64 * SPAD];
    __shared__ float bsh[64], bsh2[64];
    int tid = threadIdx.x;
    int r0 = blockIdx.x * 64;
    float epsv = 1.0f + eps_ptr[lidx];
    int part = tid & 15, grp = tid >> 4;

    #pragma unroll
    for (int rr = 0; rr < 4; rr++) {
        int row = rr * 16 + grp;
        int gr = r0 + row;
        float4 a = make_float4(0.f, 0.f, 0.f, 0.f);
        if (gr < NN) {
            float4 h = ((const float4*)(hin + (size_t)gr * HH))[part];
            a.x = epsv * h.x; a.y = epsv * h.y; a.z = epsv * h.z; a.w = epsv * h.w;
            int beg = g_off[gr], end = g_off[gr + 1];
            int p = beg;
            for (; p + 1 < end; p += 2) {
                int s0 = g_csr_src[p], s1 = g_csr_src[p + 1];
                float4 v0 = ((const float4*)(hin + (size_t)s0 * HH))[part];
                float4 v1 = ((const float4*)(hin + (size_t)s1 * HH))[part];
                a.x += v0.x + v1.x; a.y += v0.y + v1.y;
                a.z += v0.z + v1.z; a.w += v0.w + v1.w;
            }
            if (p < end) {
                int s0 = g_csr_src[p];
                float4 v0 = ((const float4*)(hin + (size_t)s0 * HH))[part];
                a.x += v0.x; a.y += v0.y; a.z += v0.z; a.w += v0.w;
            }
        }
        *((float4*)&As[row * SPAD + part * 4]) = a;
    }

    loadW(W1, Ws, tid);
    if (tid < 64) { bsh[tid] = b1[tid]; bsh2[tid] = b2[tid]; }
    __syncthreads();

    int tx = tid & 15, ty = tid >> 4;
    float acc[4][4];
    gemm64(As, Ws, Cs, acc, tid, tx, ty);
    #pragma unroll
    for (int i = 0; i < 4; i++) {
        float4 h;
        h.x = fmaxf(acc[i][0] + bsh[tx*4+0], 0.f);
        h.y = fmaxf(acc[i][1] + bsh[tx*4+1], 0.f);
        h.z = fmaxf(acc[i][2] + bsh[tx*4+2], 0.f);
        h.w = fmaxf(acc[i][3] + bsh[tx*4+3], 0.f);
        *((float4*)&As[(ty * 4 + i) * SPAD + tx * 4]) = h;
    }
    loadW(W2, Ws, tid);
    __syncthreads();
    gemm64(As, Ws, Cs, acc, tid, tx, ty);
    #pragma unroll
    for (int i = 0; i < 4; i++) {
        int go = r0 + ty * 4 + i;
        if (go < NN) {
            float4 o;
            o.x = fmaxf(acc[i][0] + bsh2[tx*4+0], 0.f);
            o.y = fmaxf(acc[i][1] + bsh2[tx*4+1], 0.f);
            o.z = fmaxf(acc[i][2] + bsh2[tx*4+2], 0.f);
            o.w = fmaxf(acc[i][3] + bsh2[tx*4+3], 0.f);
            *((float4*)(hout + (size_t)go * HH + tx * 4)) = o;
            if (pool) {
                int b = batch[go];
                red_add_f4((float4*)(pool + (size_t)b * HH + tx * 4), o);
            }
        }
    }
}

// ---------------- classifier GIN layer, all K experts, interleaved [n][k][64] ----------
__global__ __launch_bounds__(256) void gincl_kernel(
    const float* __restrict__ hin, float* __restrict__ hout,
    const float* __restrict__ eps_ptr, int lidx,
    const float* __restrict__ W1, const float* __restrict__ b1,
    const float* __restrict__ W2, const float* __restrict__ b2,
    float* __restrict__ pool, const int* __restrict__ batch)
{
    __shared__ __align__(16) float As[64 * SPAD];
    __shared__ __align__(16) float Ws[64 * SPAD];
    __shared__ __align__(16) float Cs[64 * SPAD];
    __shared__ float bsh[64], bsh2[64];
    int tid = threadIdx.x;
    int n0 = blockIdx.x * 16;
    float epsv = 1.0f + eps_ptr[lidx];
    int part = tid & 15, grp = tid >> 4;

    {
        int gr = n0 + grp;
        const float4* hbase = (const float4*)(hin + (size_t)gr * KK * HH);
        float4 a[4];
        #pragma unroll
        for (int k = 0; k < 4; k++) {
            float4 h = hbase[k * 16 + part];
            a[k].x = epsv * h.x; a[k].y = epsv * h.y;
            a[k].z = epsv * h.z; a[k].w = epsv * h.w;
        }
        int beg = g_off[gr], end = g_off[gr + 1];
        int p = beg;
        int s_next = (p < end) ? g_csr_src[p] : 0;
        for (; p < end; p++) {
            int s = s_next;
            if (p + 1 < end) s_next = g_csr_src[p + 1];
            float4 w4 = *((const float4*)(g_ewc + (size_t)p * 4));
            const float4* vb = (const float4*)(hin + (size_t)s * KK * HH);
            float4 v0 = vb[0 * 16 + part];
            float4 v1 = vb[1 * 16 + part];
            float4 v2 = vb[2 * 16 + part];
            float4 v3 = vb[3 * 16 + part];
            a[0].x = fmaf(w4.x, v0.x, a[0].x); a[0].y = fmaf(w4.x, v0.y, a[0].y);
            a[0].z = fmaf(w4.x, v0.z, a[0].z); a[0].w = fmaf(w4.x, v0.w, a[0].w);
            a[1].x = fmaf(w4.y, v1.x, a[1].x); a[1].y = fmaf(w4.y, v1.y, a[1].y);
            a[1].z = fmaf(w4.y, v1.z, a[1].z); a[1].w = fmaf(w4.y, v1.w, a[1].w);
            a[2].x = fmaf(w4.z, v2.x, a[2].x); a[2].y = fmaf(w4.z, v2.y, a[2].y);
            a[2].z = fmaf(w4.z, v2.z, a[2].z); a[2].w = fmaf(w4.z, v2.w, a[2].w);
            a[3].x = fmaf(w4.w, v3.x, a[3].x); a[3].y = fmaf(w4.w, v3.y, a[3].y);
            a[3].z = fmaf(w4.w, v3.z, a[3].z); a[3].w = fmaf(w4.w, v3.w, a[3].w);
        }
        #pragma unroll
        for (int k = 0; k < 4; k++)
            *((float4*)&As[(grp * 4 + k) * SPAD + part * 4]) = a[k];
    }

    loadW(W1, Ws, tid);
    if (tid < 64) { bsh[tid] = b1[tid]; bsh2[tid] = b2[tid]; }
    __syncthreads();

    int tx = tid & 15, ty = tid >> 4;
    float acc[4][4];
    gemm64(As, Ws, Cs, acc, tid, tx, ty);
    #pragma unroll
    for (int i = 0; i < 4; i++) {
        float4 h;
        h.x = fmaxf(acc[i][0] + bsh[tx*4+0], 0.f);
        h.y = fmaxf(acc[i][1] + bsh[tx*4+1], 0.f);
        h.z = fmaxf(acc[i][2] + bsh[tx*4+2], 0.f);
        h.w = fmaxf(acc[i][3] + bsh[tx*4+3], 0.f);
        *((float4*)&As[(ty * 4 + i) * SPAD + tx * 4]) = h;
    }
    loadW(W2, Ws, tid);
    __syncthreads();
    gemm64(As, Ws, Cs, acc, tid, tx, ty);
    #pragma unroll
    for (int i = 0; i < 4; i++) {
        int row = ty * 4 + i;
        int gn = n0 + (row >> 2);
        int ke = row & 3;
        float4 o;
        o.x = fmaxf(acc[i][0] + bsh2[tx*4+0], 0.f);
        o.y = fmaxf(acc[i][1] + bsh2[tx*4+1], 0.f);
        o.z = fmaxf(acc[i][2] + bsh2[tx*4+2], 0.f);
        o.w = fmaxf(acc[i][3] + bsh2[tx*4+3], 0.f);
        *((float4*)(hout + ((size_t)gn * KK + ke) * HH + tx * 4)) = o;
        if (pool) {
            int b = batch[gn];
            red_add_f4((float4*)(pool + ((size_t)ke * NB_BATCH + b) * HH + tx * 4), o);
        }
    }
}

// ---------------- fused mask kernel: nm + AB precompute + fm + masked_x ----------------
__global__ __launch_bounds__(256) void mask_kernel(
    const float* __restrict__ Z, const float* __restrict__ x,
    const float* __restrict__ nmW1, const float* __restrict__ nmb1,
    const float* __restrict__ nmW2, const float* __restrict__ nmb2,
    const float* __restrict__ emW1,
    const float* __restrict__ fmW1, const float* __restrict__ fmb1,
    const float* __restrict__ fmW2, const float* __restrict__ fmb2,
    float* __restrict__ out_nm, float* __restrict__ out_fm)
{
    __shared__ __align__(16) float As[64 * SPAD];
    __shared__ __align__(16) float Ws[64 * SPAD];
    __shared__ __align__(16) float Cs[64 * SPAD];
    __shared__ float bsh[64], bsh2[64], w2s[64], nmv[64];
    int tid = threadIdx.x, r0 = blockIdx.x * 64;
    int k = blockIdx.y;
    const float* nmW1k = nmW1 + (size_t)k * 4096;
    const float* nmb1k = nmb1 + (size_t)k * 64;
    const float* nmW2k = nmW2 + (size_t)k * 64;
    const float* emW1k = emW1 + (size_t)k * 8192;
    const float* fmW1k = fmW1 + (size_t)k * 4096;
    const float* fmb1k = fmb1 + (size_t)k * 64;
    const float* fmW2k = fmW2 + (size_t)k * 4096;
    const float* fmb2k = fmb2 + (size_t)k * 64;
    float* ABk = g_AB + (size_t)k * NN * 128;

    {
        int row = tid >> 2, p0 = (tid & 3) * 4, gr = r0 + row;
        #pragma unroll
        for (int q = 0; q < 4; q++) {
            float4 v = make_float4(0.f, 0.f, 0.f, 0.f);
            if (gr < NN) v = ((const float4*)(Z + (size_t)gr * HH))[p0 + q];
            *((float4*)&As[row * SPAD + (p0 + q) * 4]) = v;
        }
    }
    int tx = tid & 15, ty = tid >> 4;
    float acc[4][4];

    // ---- node mask ----
    loadW(nmW1k, Ws, tid);
    if (tid < 64) { bsh[tid] = nmb1k[tid]; w2s[tid] = nmW2k[tid]; }
    __syncthreads();
    gemm64(As, Ws, Cs, acc, tid, tx, ty);
    float b2v = nmb2[k];
    #pragma unroll
    for (int i = 0; i < 4; i++) {
        float p = 0.f;
        #pragma unroll
        for (int j = 0; j < 4; j++)
            p += fmaxf(acc[i][j] + bsh[tx*4+j], 0.f) * w2s[tx*4+j];
        #pragma unroll
        for (int off = 8; off > 0; off >>= 1)
            p += __shfl_down_sync(0xffffffffu, p, off, 16);
        if (tx == 0) {
            float sg = sigmoidf_(p + b2v);
            nmv[ty * 4 + i] = sg;
            int gr = r0 + ty * 4 + i;
            if (gr < NN) out_nm[(size_t)gr * KK + k] = sg;
        }
    }

    // ---- AB precompute ----
    #pragma unroll
    for (int half = 0; half < 2; half++) {
        __syncthreads();
        loadW(emW1k + half * 4096, Ws, tid);
        __syncthreads();
        gemm64(As, Ws, Cs, acc, tid, tx, ty);
        #pragma unroll
        for (int i = 0; i < 4; i++) {
            int gr = r0 + ty * 4 + i;
            if (gr < NN) {
                float4 o = make_float4(acc[i][0], acc[i][1], acc[i][2], acc[i][3]);
                *((float4*)(ABk + (size_t)gr * 128 + half * 64 + tx * 4)) = o;
            }
        }
    }

    // ---- feature mask + masked_x (interleaved h0 store) ----
    __syncthreads();
    loadW(fmW1k, Ws, tid);
    if (tid < 64) { bsh[tid] = fmb1k[tid]; bsh2[tid] = fmb2k[tid]; }
    __syncthreads();
    gemm64(As, Ws, Cs, acc, tid, tx, ty);
    #pragma unroll
    for (int i = 0; i < 4; i++) {
        float4 h;
        h.x = fmaxf(acc[i][0] + bsh[tx*4+0], 0.f);
        h.y = fmaxf(acc[i][1] + bsh[tx*4+1], 0.f);
        h.z = fmaxf(acc[i][2] + bsh[tx*4+2], 0.f);
        h.w = fmaxf(acc[i][3] + bsh[tx*4+3], 0.f);
        *((float4*)&As[(ty * 4 + i) * SPAD + tx * 4]) = h;
    }
    loadW(fmW2k, Ws, tid);
    __syncthreads();
    gemm64(As, Ws, Cs, acc, tid, tx, ty);
    #pragma unroll
    for (int i = 0; i < 4; i++) {
        int gr = r0 + ty * 4 + i;
        if (gr < NN) {
            float nmu = nmv[ty * 4 + i];
            float4 xr = *((const float4*)(x + (size_t)gr * FF + tx * 4));
            float4 sg;
            sg.x = sigmoidf_(acc[i][0] + bsh2[tx*4+0]);
            sg.y = sigmoidf_(acc[i][1] + bsh2[tx*4+1]);
            sg.z = sigmoidf_(acc[i][2] + bsh2[tx*4+2]);
            sg.w = sigmoidf_(acc[i][3] + bsh2[tx*4+3]);
            *((float4*)(out_fm + ((size_t)gr * KK + k) * FF + tx * 4)) = sg;
            float4 m = make_float4(xr.x * nmu * sg.x, xr.y * nmu * sg.y,
                                   xr.z * nmu * sg.z, xr.w * nmu * sg.w);
            *((float4*)(g_h0 + ((size_t)gr * KK + k) * HH + tx * 4)) = m;
        }
    }
}

// ---------------- edge mask: 16 lanes/edge, iterating CSR positions ----------
__global__ __launch_bounds__(256) void edge_mask_kernel(
    const float* __restrict__ emb1, const float* __restrict__ emW2,
    const float* __restrict__ emb2, float* __restrict__ out_em)
{
    __shared__ __align__(16) float b1s[64];
    __shared__ __align__(16) float w2s[64];
    int tid = threadIdx.x;
    int k = blockIdx.y;
    if (tid < 64) { b1s[tid] = emb1[k * 64 + tid]; w2s[tid] = emW2[k * 64 + tid]; }
    __syncthreads();
    const float* ABk = g_AB + (size_t)k * NN * 128;
    int idx = blockIdx.x * 256 + tid;
    int p = idx >> 4, lane = idx & 15;
    int s = g_csr_src[p], d = g_csr_dst[p];
    float4 a  = *((const float4*)(ABk + (size_t)s * 128) + lane);
    float4 bb = *((const float4*)(ABk + (size_t)d * 128 + 64) + lane);
    float4 bi = ((const float4*)b1s)[lane];
    float4 w  = ((const float4*)w2s)[lane];
    float pp = fmaxf(a.x + bb.x + bi.x, 0.f) * w.x
             + fmaxf(a.y + bb.y + bi.y, 0.f) * w.y
             + fmaxf(a.z + bb.z + bi.z, 0.f) * w.z
             + fmaxf(a.w + bb.w + bi.w, 0.f) * w.w;
    #pragma unroll
    for (int off = 8; off > 0; off >>= 1)
        pp += __shfl_down_sync(0xffffffffu, pp, off, 16);
    if (lane == 0) {
        float sg = sigmoidf_(pp + emb2[k]);
        g_ewc[(size_t)p * KK + k] = sg;
        out_em[(size_t)g_csr_eid[p] * KK + k] = sg;
    }
}

// ---------------- finalize ----------------
__global__ __launch_bounds__(64) void finalize_kernel(
    const float* __restrict__ clfW, const float* __restrict__ clfb,
    float* __restrict__ out_logits, float* __restrict__ out_hstab,
    float* __restrict__ out_horig)
{
    int b = blockIdx.x, t = threadIdx.x;
    __shared__ float hs[64];
    float inv = 1.0f / fmaxf((float)g_cnt[b], 1.0f);
    out_horig[b * HH + t] = g_poolZ[b * HH + t] * inv;
    for (int k = 0; k < KK; k++) {
        float v = g_poolS[((size_t)k * NB_BATCH + b) * HH + t] * inv;
        out_hstab[((size_t)b * KK + k) * HH + t] = v;
        hs[t] = v;
        __syncthreads();
        if (t < CC) {
            float sacc = clfb[k * CC + t];
            #pragma unroll 8
            for (int h2 = 0; h2 < HH; h2++)
                sacc += hs[h2] * clfW[((size_t)k * HH + h2) * CC + t];
            out_logits[((size_t)b * KK + k) * CC + t] = sacc;
        }
        __syncthreads();
    }
}

// ---------------- host launch ----------------
extern "C" void kernel_launch(void* const* d_in, const int* in_sizes, int n_in,
                              void* d_out, int out_size)
{
    const float* x     = (const float*)d_in[0];
    const int*   ei    = (const int*)d_in[1];
    const int*   batch = (const int*)d_in[2];
    const float* ceW1  = (const float*)d_in[3];
    const float* ceb1  = (const float*)d_in[4];
    const float* ceW2  = (const float*)d_in[5];
    const float* ceb2  = (const float*)d_in[6];
    const float* ceeps = (const float*)d_in[7];
    const float* clW1  = (const float*)d_in[8];
    const float* clb1  = (const float*)d_in[9];
    const float* clW2  = (const float*)d_in[10];
    const float* clb2  = (const float*)d_in[11];
    const float* cleps = (const float*)d_in[12];
    const float* nmW1  = (const float*)d_in[13];
    const float* nmb1  = (const float*)d_in[14];
    const float* nmW2  = (const float*)d_in[15];
    const float* nmb2  = (const float*)d_in[16];
    const float* emW1  = (const float*)d_in[17];
    const float* emb1  = (const float*)d_in[18];
    const float* emW2  = (const float*)d_in[19];
    const float* emb2  = (const float*)d_in[20];
    const float* fmW1  = (const float*)d_in[21];
    const float* fmb1  = (const float*)d_in[22];
    const float* fmW2  = (const float*)d_in[23];
    const float* fmb2  = (const float*)d_in[24];
    const float* clfW  = (const float*)d_in[25];
    const float* clfb  = (const float*)d_in[26];

    const int* src = ei;
    const int* dst = ei + EE;

    float* Z_p;     cudaGetSymbolAddress((void**)&Z_p, g_Z);
    float* h0_p;    cudaGetSymbolAddress((void**)&h0_p, g_h0);
    float* h1_p;    cudaGetSymbolAddress((void**)&h1_p, g_h1);
    float* poolZ_p; cudaGetSymbolAddress((void**)&poolZ_p, g_poolZ);
    float* poolS_p; cudaGetSymbolAddress((void**)&poolS_p, g_poolS);

    float* out        = (float*)d_out;
    float* out_logits = out;
    float* out_hstab  = out_logits + NB_BATCH * KK * CC;
    float* out_horig  = out_hstab + NB_BATCH * KK * HH;
    float* out_nm     = out_horig + NB_BATCH * HH;
    float* out_em     = out_nm + (size_t)NN * KK;
    float* out_fm     = out_em + (size_t)EE * KK;

    const int GB = (NN + 63) / 64;          // 782
    const int GC = NN / 16;                 // 3125
    const int EG = (EE + 255) / 256;        // 3125
    const int EDGE_GRID = (EE * 16) / 256;  // 50000
    const int IG = (KK * NB_BATCH * HH + 255) / 256;

    // ---- CSR build + init ----
    init_kernel<<<IG, 256>>>();
    histcnt_kernel<<<EG, 256>>>(dst, batch);
    scan_kernel<<<1, 1024>>>();
    fill_kernel<<<EG, 256>>>(src, dst);

    // ---- causal encoder GIN (3 layers); layer 3 fuses Z pooling ----
    ginenc_kernel<<<GB, 256>>>(x, h1_p, ceeps, 0, ceW1, ceb1, ceW2, ceb2, nullptr, nullptr);
    ginenc_kernel<<<GB, 256>>>(h1_p, h0_p, ceeps, 1, ceW1 + 4096, ceb1 + 64,
                               ceW2 + 4096, ceb2 + 64, nullptr, nullptr);
    ginenc_kernel<<<GB, 256>>>(h0_p, Z_p, ceeps, 2, ceW1 + 8192, ceb1 + 128,
                               ceW2 + 8192, ceb2 + 128, poolZ_p, batch);

    // ---- masks (writes interleaved g_h0) ----
    mask_kernel<<<dim3(GB, KK), 256>>>(Z_p, x, nmW1, nmb1, nmW2, nmb2,
                                       emW1, fmW1, fmb1, fmW2, fmb2,
                                       out_nm, out_fm);
    edge_mask_kernel<<<dim3(EDGE_GRID, KK), 256>>>(emb1, emW2, emb2, out_em);

    // ---- classifier GIN (3 layers, all K); layer 3 fuses pooling ----
    gincl_kernel<<<GC, 256>>>(h0_p, h1_p, cleps, 0, clW1, clb1, clW2, clb2,
                              nullptr, nullptr);
    gincl_kernel<<<GC, 256>>>(h1_p, h0_p, cleps, 1, clW1 + 4096, clb1 + 64,
                              clW2 + 4096, clb2 + 64, nullptr, nullptr);
    gincl_kernel<<<GC, 256>>>(h0_p, h1_p, cleps, 2, clW1 + 8192, clb1 + 128,
                              clW2 + 8192, clb2 + 128, poolS_p, batch);

    // ---- finalize ----
    finalize_kernel<<<NB_BATCH, 64>>>(clfW, clfb, out_logits, out_hstab, out_horig);
}

// round 12
// speedup vs baseline: 1.0861x; 1.0240x over previous
#include <cuda_runtime.h>
#include <math.h>
#include <stdint.h>

#define NN 50000
#define EE 800000
#define HH 64
#define FF 64
#define CC 10
#define KK 4
#define LL 3
#define NB_BATCH 256
#define SPAD 68
#define WSPAD 72   // weight smem stride: (8*lc+lr)%32 unique -> conflict-free B loads

// ---------------- device scratch ----------------
__device__ float g_Z[NN * HH];
__device__ float g_h0[(size_t)NN * KK * HH];   // interleaved [n][k][64]
__device__ float g_h1[(size_t)NN * KK * HH];   // interleaved [n][k][64]
__device__ float g_AB[(size_t)KK * NN * 128];
__device__ float g_ewc[(size_t)EE * KK];       // CSR-edge-major weights [p][k]
__device__ int   g_deg[NN];
__device__ int   g_off[NN + 1];
__device__ int   g_fill[NN];
__device__ int   g_csr_src[EE];
__device__ int   g_csr_dst[EE];
__device__ int   g_csr_eid[EE];
__device__ float g_poolZ[NB_BATCH * HH];
__device__ float g_poolS[KK * NB_BATCH * HH];
__device__ int   g_cnt[NB_BATCH];

__device__ __forceinline__ void red_add_f4(float4* p, float4 v) {
    asm volatile("red.global.add.v4.f32 [%0], {%1,%2,%3,%4};"
                 :: "l"(p), "f"(v.x), "f"(v.y), "f"(v.z), "f"(v.w) : "memory");
}
__device__ __forceinline__ float sigmoidf_(float v) { return 1.0f / (1.0f + expf(-v)); }

__device__ __forceinline__ uint32_t tf32_rna(float a) {
    uint32_t h; asm("cvt.rna.tf32.f32 %0, %1;" : "=r"(h) : "f"(a)); return h;
}

// Split 64x64 row-major W into tf32 hi/lo planes (stride WSPAD, conflict-free).
__device__ __forceinline__ void loadWsplit(const float* __restrict__ W,
                                           float* Wh, float* Wl, int tid) {
    for (int i = tid; i < 1024; i += 256) {
        float4 w = ((const float4*)W)[i];
        int k = i >> 4, j = (i & 15) * 4;
        float4 h, l;
        h.x = __uint_as_float(tf32_rna(w.x)); l.x = __uint_as_float(tf32_rna(w.x - h.x));
        h.y = __uint_as_float(tf32_rna(w.y)); l.y = __uint_as_float(tf32_rna(w.y - h.y));
        h.z = __uint_as_float(tf32_rna(w.z)); l.z = __uint_as_float(tf32_rna(w.z - h.z));
        h.w = __uint_as_float(tf32_rna(w.w)); l.w = __uint_as_float(tf32_rna(w.w - h.w));
        *((float4*)&Wh[k * WSPAD + j]) = h;
        *((float4*)&Wl[k * WSPAD + j]) = l;
    }
}

#define MMA_TF32(c, A0, A1, A2, A3, B0, B1) \
    asm("mma.sync.aligned.m16n8k8.row.col.f32.tf32.tf32.f32 " \
        "{%0,%1,%2,%3}, {%4,%5,%6,%7}, {%8,%9}, {%0,%1,%2,%3};" \
        : "+f"((c)[0]), "+f"((c)[1]), "+f"((c)[2]), "+f"((c)[3]) \
        : "r"(A0), "r"(A1), "r"(A2), "r"(A3), "r"(B0), "r"(B1))

// Fragment GEMM: As row-major [row][k] (SPAD), weights pre-split in Wh/Wl (WSPAD).
// c[nt][q]: rows mband+lr (q0,q1) / mband+8+lr (q2,q3), cols nhalf+nt*8+lc*2 (+1).
__device__ __forceinline__ void gemm_frag(const float* As, const float* Wh,
                                          const float* Wl, float c[4][4],
                                          int lane, int warp) {
    int mband = (warp & 3) * 16, nhalf = (warp >> 2) * 32;
    int lr = lane >> 2, lc = lane & 3;
    #pragma unroll
    for (int nt = 0; nt < 4; nt++)
        #pragma unroll
        for (int q = 0; q < 4; q++) c[nt][q] = 0.f;
    #pragma unroll
    for (int ks = 0; ks < 8; ks++) {
        int k0 = ks * 8;
        float a0 = As[(mband + lr) * SPAD + k0 + lc];
        float a1 = As[(mband + 8 + lr) * SPAD + k0 + lc];
        float a2 = As[(mband + lr) * SPAD + k0 + 4 + lc];
        float a3 = As[(mband + 8 + lr) * SPAD + k0 + 4 + lc];
        uint32_t ah0 = tf32_rna(a0), ah1 = tf32_rna(a1);
        uint32_t ah2 = tf32_rna(a2), ah3 = tf32_rna(a3);
        uint32_t al0 = tf32_rna(a0 - __uint_as_float(ah0));
        uint32_t al1 = tf32_rna(a1 - __uint_as_float(ah1));
        uint32_t al2 = tf32_rna(a2 - __uint_as_float(ah2));
        uint32_t al3 = tf32_rna(a3 - __uint_as_float(ah3));
        #pragma unroll
        for (int nt = 0; nt < 4; nt++) {
            int n = nhalf + nt * 8 + lr;
            uint32_t bh0 = __float_as_uint(Wh[(k0 + lc) * WSPAD + n]);
            uint32_t bl0 = __float_as_uint(Wl[(k0 + lc) * WSPAD + n]);
            uint32_t bh1 = __float_as_uint(Wh[(k0 + 4 + lc) * WSPAD + n]);
            uint32_t bl1 = __float_as_uint(Wl[(k0 + 4 + lc) * WSPAD + n]);
            MMA_TF32(c[nt], ah0, ah1, ah2, ah3, bh0, bh1);
            MMA_TF32(c[nt], al0, al1, al2, al3, bh0, bh1);
            MMA_TF32(c[nt], ah0, ah1, ah2, ah3, bl0, bl1);
        }
    }
}

// Stage fragments into a scratch region (legacy SPAD layout).
__device__ __forceinline__ void stage_frag(const float c[4][4], float* Cs,
                                           int lane, int warp) {
    int mband = (warp & 3) * 16, nhalf = (warp >> 2) * 32;
    int lr = lane >> 2, lc = lane & 3;
    #pragma unroll
    for (int nt = 0; nt < 4; nt++) {
        int col = nhalf + nt * 8 + lc * 2;
        *((float2*)&Cs[(mband + lr) * SPAD + col])     = make_float2(c[nt][0], c[nt][1]);
        *((float2*)&Cs[(mband + 8 + lr) * SPAD + col]) = make_float2(c[nt][2], c[nt][3]);
    }
}

__device__ __forceinline__ void read_acc(const float* Cs, float acc[4][4],
                                         int tx, int ty) {
    #pragma unroll
    for (int i = 0; i < 4; i++) {
        float4 v = *((const float4*)&Cs[(ty * 4 + i) * SPAD + tx * 4]);
        acc[i][0] = v.x; acc[i][1] = v.y; acc[i][2] = v.z; acc[i][3] = v.w;
    }
}

// Mid-layer epilogue, fragment-direct: As = relu(c + b) (no staging).
__device__ __forceinline__ void frag_relu_to_As(const float c[4][4], const float* bsh,
                                                float* As, int lane, int warp) {
    int mband = (warp & 3) * 16, nhalf = (warp >> 2) * 32;
    int lr = lane >> 2, lc = lane & 3;
    #pragma unroll
    for (int nt = 0; nt < 4; nt++) {
        int col = nhalf + nt * 8 + lc * 2;
        float b0 = bsh[col], b1 = bsh[col + 1];
        *((float2*)&As[(mband + lr) * SPAD + col]) =
            make_float2(fmaxf(c[nt][0] + b0, 0.f), fmaxf(c[nt][1] + b1, 0.f));
        *((float2*)&As[(mband + 8 + lr) * SPAD + col]) =
            make_float2(fmaxf(c[nt][2] + b0, 0.f), fmaxf(c[nt][3] + b1, 0.f));
    }
}

// ---------------- init ----------------
__global__ __launch_bounds__(256) void init_kernel() {
    int i = blockIdx.x * 256 + threadIdx.x;
    if (i < NN) { g_deg[i] = 0; g_fill[i] = 0; }
    if (i < NB_BATCH) g_cnt[i] = 0;
    if (i < NB_BATCH * HH) g_poolZ[i] = 0.f;
    if (i < KK * NB_BATCH * HH) g_poolS[i] = 0.f;
}

__global__ __launch_bounds__(256) void histcnt_kernel(const int* __restrict__ dst,
                                                      const int* __restrict__ batch) {
    int e = blockIdx.x * 256 + threadIdx.x;
    if (e < EE) atomicAdd(&g_deg[dst[e]], 1);
    if (e < NN) atomicAdd(&g_cnt[batch[e]], 1);
}

__global__ __launch_bounds__(1024) void scan_kernel() {
    __shared__ int wsum[32];
    __shared__ int carry_s;
    int tid = threadIdx.x, lane = tid & 31, wid = tid >> 5;
    if (tid == 0) carry_s = 0;
    __syncthreads();
    for (int base = 0; base < NN; base += 1024) {
        int v = (base + tid < NN) ? g_deg[base + tid] : 0;
        int inc = v;
        #pragma unroll
        for (int off = 1; off < 32; off <<= 1) {
            int t = __shfl_up_sync(0xffffffffu, inc, off);
            if (lane >= off) inc += t;
        }
        if (lane == 31) wsum[wid] = inc;
        __syncthreads();
        if (wid == 0) {
            int s = wsum[lane];
            #pragma unroll
            for (int off = 1; off < 32; off <<= 1) {
                int t = __shfl_up_sync(0xffffffffu, s, off);
                if (lane >= off) s += t;
            }
            wsum[lane] = s;
        }
        __syncthreads();
        int wpre = wid ? wsum[wid - 1] : 0;
        int excl = carry_s + wpre + inc - v;
        if (base + tid < NN) g_off[base + tid] = excl;
        __syncthreads();
        if (tid == 0) carry_s += wsum[31];
        __syncthreads();
    }
    if (threadIdx.x == 0) g_off[NN] = carry_s;
}

__global__ __launch_bounds__(256) void fill_kernel(const int* __restrict__ src,
                                                   const int* __restrict__ dst) {
    int e = blockIdx.x * 256 + threadIdx.x;
    if (e < EE) {
        int d = dst[e];
        int pos = g_off[d] + atomicAdd(&g_fill[d], 1);
        g_csr_src[pos] = src[e];
        g_csr_dst[pos] = d;
        g_csr_eid[pos] = e;
    }
}

// ---------------- encoder GIN layer ----------------
__global__ __launch_bounds__(256) void ginenc_kernel(
    const float* __restrict__ hin, float* __restrict__ hout,
    const float* __restrict__ eps_ptr, int lidx,
    const float* __restrict__ W1, const float* __restrict__ b1,
    const float* __restrict__ W2, const float* __restrict__ b2,
    float* __restrict__ pool, const int* __restrict__ batch)
{
    __shared__ __align__(16) float As[64 * SPAD];
    __shared__ __align__(16) float Wh[64 * WSPAD];
    __shared__ __align__(16) float Wl[64 * WSPAD];
    __shared__ float bsh[64], bsh2[64];
    int tid = threadIdx.x;
    int r0 = blockIdx.x * 64;
    float epsv = 1.0f + eps_ptr[lidx];
    int part = tid & 15, grp = tid >> 4;
    int lane = tid & 31, warp = tid >> 5;

    #pragma unroll
    for (int rr = 0; rr < 4; rr++) {
        int row = rr * 16 + grp;
        int gr = r0 + row;
        float4 a = make_float4(0.f, 0.f, 0.f, 0.f);
        if (gr < NN) {
            float4 h = ((const float4*)(hin + (size_t)gr * HH))[part];
            a.x = epsv * h.x; a.y = epsv * h.y; a.z = epsv * h.z; a.w = epsv * h.w;
            int beg = g_off[gr], end = g_off[gr + 1];
            int p = beg;
            for (; p + 1 < end; p += 2) {
                int s0 = g_csr_src[p], s1 = g_csr_src[p + 1];
                float4 v0 = ((const float4*)(hin + (size_t)s0 * HH))[part];
                float4 v1 = ((const float4*)(hin + (size_t)s1 * HH))[part];
                a.x += v0.x + v1.x; a.y += v0.y + v1.y;
                a.z += v0.z + v1.z; a.w += v0.w + v1.w;
            }
            if (p < end) {
                int s0 = g_csr_src[p];
                float4 v0 = ((const float4*)(hin + (size_t)s0 * HH))[part];
                a.x += v0.x; a.y += v0.y; a.z += v0.z; a.w += v0.w;
            }
        }
        *((float4*)&As[row * SPAD + part * 4]) = a;
    }

    loadWsplit(W1, Wh, Wl, tid);
    if (tid < 64) { bsh[tid] = b1[tid]; bsh2[tid] = b2[tid]; }
    __syncthreads();

    int tx = tid & 15, ty = tid >> 4;
    float c[4][4];
    gemm_frag(As, Wh, Wl, c, lane, warp);
    __syncthreads();
    frag_relu_to_As(c, bsh, As, lane, warp);
    loadWsplit(W2, Wh, Wl, tid);
    __syncthreads();
    gemm_frag(As, Wh, Wl, c, lane, warp);
    __syncthreads();
    stage_frag(c, Wh, lane, warp);   // W2 consumed; reuse as staging
    __syncthreads();
    float acc[4][4];
    read_acc(Wh, acc, tx, ty);
    #pragma unroll
    for (int i = 0; i < 4; i++) {
        int go = r0 + ty * 4 + i;
        if (go < NN) {
            float4 o;
            o.x = fmaxf(acc[i][0] + bsh2[tx*4+0], 0.f);
            o.y = fmaxf(acc[i][1] + bsh2[tx*4+1], 0.f);
            o.z = fmaxf(acc[i][2] + bsh2[tx*4+2], 0.f);
            o.w = fmaxf(acc[i][3] + bsh2[tx*4+3], 0.f);
            *((float4*)(hout + (size_t)go * HH + tx * 4)) = o;
            if (pool) {
                int b = batch[go];
                red_add_f4((float4*)(pool + (size_t)b * HH + tx * 4), o);
            }
        }
    }
}

// ---------------- classifier GIN layer ----------------
__global__ __launch_bounds__(256) void gincl_kernel(
    const float* __restrict__ hin, float* __restrict__ hout,
    const float* __restrict__ eps_ptr, int lidx,
    const float* __restrict__ W1, const float* __restrict__ b1,
    const float* __restrict__ W2, const float* __restrict__ b2,
    float* __restrict__ pool, const int* __restrict__ batch)
{
    __shared__ __align__(16) float As[64 * SPAD];
    __shared__ __align__(16) float Wh[64 * WSPAD];
    __shared__ __align__(16) float Wl[64 * WSPAD];
    __shared__ float bsh[64], bsh2[64];
    int tid = threadIdx.x;
    int n0 = blockIdx.x * 16;
    float epsv = 1.0f + eps_ptr[lidx];
    int part = tid & 15, grp = tid >> 4;
    int lane = tid & 31, warp = tid >> 5;

    {
        int gr = n0 + grp;
        const float4* hbase = (const float4*)(hin + (size_t)gr * KK * HH);
        float4 a[4];
        #pragma unroll
        for (int k = 0; k < 4; k++) {
            float4 h = hbase[k * 16 + part];
            a[k].x = epsv * h.x; a[k].y = epsv * h.y;
            a[k].z = epsv * h.z; a[k].w = epsv * h.w;
        }
        int beg = g_off[gr], end = g_off[gr + 1];
        int p = beg;
        int s_next = (p < end) ? g_csr_src[p] : 0;
        for (; p < end; p++) {
            int s = s_next;
            if (p + 1 < end) s_next = g_csr_src[p + 1];
            float4 w4 = *((const float4*)(g_ewc + (size_t)p * 4));
            const float4* vb = (const float4*)(hin + (size_t)s * KK * HH);
            float4 v0 = vb[0 * 16 + part];
            float4 v1 = vb[1 * 16 + part];
            float4 v2 = vb[2 * 16 + part];
            float4 v3 = vb[3 * 16 + part];
            a[0].x = fmaf(w4.x, v0.x, a[0].x); a[0].y = fmaf(w4.x, v0.y, a[0].y);
            a[0].z = fmaf(w4.x, v0.z, a[0].z); a[0].w = fmaf(w4.x, v0.w, a[0].w);
            a[1].x = fmaf(w4.y, v1.x, a[1].x); a[1].y = fmaf(w4.y, v1.y, a[1].y);
            a[1].z = fmaf(w4.y, v1.z, a[1].z); a[1].w = fmaf(w4.y, v1.w, a[1].w);
            a[2].x = fmaf(w4.z, v2.x, a[2].x); a[2].y = fmaf(w4.z, v2.y, a[2].y);
            a[2].z = fmaf(w4.z, v2.z, a[2].z); a[2].w = fmaf(w4.z, v2.w, a[2].w);
            a[3].x = fmaf(w4.w, v3.x, a[3].x); a[3].y = fmaf(w4.w, v3.y, a[3].y);
            a[3].z = fmaf(w4.w, v3.z, a[3].z); a[3].w = fmaf(w4.w, v3.w, a[3].w);
        }
        #pragma unroll
        for (int k = 0; k < 4; k++)
            *((float4*)&As[(grp * 4 + k) * SPAD + part * 4]) = a[k];
    }

    loadWsplit(W1, Wh, Wl, tid);
    if (tid < 64) { bsh[tid] = b1[tid]; bsh2[tid] = b2[tid]; }
    __syncthreads();

    int tx = tid & 15, ty = tid >> 4;
    float c[4][4];
    gemm_frag(As, Wh, Wl, c, lane, warp);
    __syncthreads();
    frag_relu_to_As(c, bsh, As, lane, warp);
    loadWsplit(W2, Wh, Wl, tid);
    __syncthreads();
    gemm_frag(As, Wh, Wl, c, lane, warp);
    __syncthreads();
    stage_frag(c, Wh, lane, warp);
    __syncthreads();
    float acc[4][4];
    read_acc(Wh, acc, tx, ty);
    #pragma unroll
    for (int i = 0; i < 4; i++) {
        int row = ty * 4 + i;
        int gn = n0 + (row >> 2);
        int ke = row & 3;
        float4 o;
        o.x = fmaxf(acc[i][0] + bsh2[tx*4+0], 0.f);
        o.y = fmaxf(acc[i][1] + bsh2[tx*4+1], 0.f);
        o.z = fmaxf(acc[i][2] + bsh2[tx*4+2], 0.f);
        o.w = fmaxf(acc[i][3] + bsh2[tx*4+3], 0.f);
        *((float4*)(hout + ((size_t)gn * KK + ke) * HH + tx * 4)) = o;
        if (pool) {
            int b = batch[gn];
            red_add_f4((float4*)(pool + ((size_t)ke * NB_BATCH + b) * HH + tx * 4), o);
        }
    }
}

// ---------------- fused mask kernel ----------------
__global__ __launch_bounds__(256) void mask_kernel(
    const float* __restrict__ Z, const float* __restrict__ x,
    const float* __restrict__ nmW1, const float* __restrict__ nmb1,
    const float* __restrict__ nmW2, const float* __restrict__ nmb2,
    const float* __restrict__ emW1,
    const float* __restrict__ fmW1, const float* __restrict__ fmb1,
    const float* __restrict__ fmW2, const float* __restrict__ fmb2,
    float* __restrict__ out_nm, float* __restrict__ out_fm)
{
    __shared__ __align__(16) float As[64 * SPAD];
    __shared__ __align__(16) float Wh[64 * WSPAD];
    __shared__ __align__(16) float Wl[64 * WSPAD];
    __shared__ float bsh[64], bsh2[64], w2s[64], nmv[64];
    int tid = threadIdx.x, r0 = blockIdx.x * 64;
    int k = blockIdx.y;
    int lane = tid & 31, warp = tid >> 5;
    const float* nmW1k = nmW1 + (size_t)k * 4096;
    const float* nmb1k = nmb1 + (size_t)k * 64;
    const float* nmW2k = nmW2 + (size_t)k * 64;
    const float* emW1k = emW1 + (size_t)k * 8192;
    const float* fmW1k = fmW1 + (size_t)k * 4096;
    const float* fmb1k = fmb1 + (size_t)k * 64;
    const float* fmW2k = fmW2 + (size_t)k * 4096;
    const float* fmb2k = fmb2 + (size_t)k * 64;
    float* ABk = g_AB + (size_t)k * NN * 128;

    {
        int row = tid >> 2, p0 = (tid & 3) * 4, gr = r0 + row;
        #pragma unroll
        for (int q = 0; q < 4; q++) {
            float4 v = make_float4(0.f, 0.f, 0.f, 0.f);
            if (gr < NN) v = ((const float4*)(Z + (size_t)gr * HH))[p0 + q];
            *((float4*)&As[row * SPAD + (p0 + q) * 4]) = v;
        }
    }
    int tx = tid & 15, ty = tid >> 4;
    float c[4][4], acc[4][4];

    // ---- node mask ----
    loadWsplit(nmW1k, Wh, Wl, tid);
    if (tid < 64) { bsh[tid] = nmb1k[tid]; w2s[tid] = nmW2k[tid]; }
    __syncthreads();
    gemm_frag(As, Wh, Wl, c, lane, warp);
    __syncthreads();
    stage_frag(c, Wh, lane, warp);
    __syncthreads();
    read_acc(Wh, acc, tx, ty);
    float b2v = nmb2[k];
    #pragma unroll
    for (int i = 0; i < 4; i++) {
        float p = 0.f;
        #pragma unroll
        for (int j = 0; j < 4; j++)
            p += fmaxf(acc[i][j] + bsh[tx*4+j], 0.f) * w2s[tx*4+j];
        #pragma unroll
        for (int off = 8; off > 0; off >>= 1)
            p += __shfl_down_sync(0xffffffffu, p, off, 16);
        if (tx == 0) {
            float sg = sigmoidf_(p + b2v);
            nmv[ty * 4 + i] = sg;
            int gr = r0 + ty * 4 + i;
            if (gr < NN) out_nm[(size_t)gr * KK + k] = sg;
        }
    }
    __syncthreads();

    // ---- AB precompute ----
    #pragma unroll
    for (int half = 0; half < 2; half++) {
        loadWsplit(emW1k + half * 4096, Wh, Wl, tid);
        __syncthreads();
        gemm_frag(As, Wh, Wl, c, lane, warp);
        __syncthreads();
        stage_frag(c, Wh, lane, warp);
        __syncthreads();
        read_acc(Wh, acc, tx, ty);
        #pragma unroll
        for (int i = 0; i < 4; i++) {
            int gr = r0 + ty * 4 + i;
            if (gr < NN) {
                float4 o = make_float4(acc[i][0], acc[i][1], acc[i][2], acc[i][3]);
                *((float4*)(ABk + (size_t)gr * 128 + half * 64 + tx * 4)) = o;
            }
        }
        __syncthreads();
    }

    // ---- feature mask + masked_x ----
    loadWsplit(fmW1k, Wh, Wl, tid);
    if (tid < 64) { bsh[tid] = fmb1k[tid]; bsh2[tid] = fmb2k[tid]; }
    __syncthreads();
    gemm_frag(As, Wh, Wl, c, lane, warp);   // last use of Z tile
    __syncthreads();
    frag_relu_to_As(c, bsh, As, lane, warp);
    loadWsplit(fmW2k, Wh, Wl, tid);
    __syncthreads();
    gemm_frag(As, Wh, Wl, c, lane, warp);
    __syncthreads();
    stage_frag(c, Wh, lane, warp);
    __syncthreads();
    read_acc(Wh, acc, tx, ty);
    #pragma unroll
    for (int i = 0; i < 4; i++) {
        int gr = r0 + ty * 4 + i;
        if (gr < NN) {
            float nmu = nmv[ty * 4 + i];
            float4 xr = *((const float4*)(x + (size_t)gr * FF + tx * 4));
            float4 sg;
            sg.x = sigmoidf_(acc[i][0] + bsh2[tx*4+0]);
            sg.y = sigmoidf_(acc[i][1] + bsh2[tx*4+1]);
            sg.z = sigmoidf_(acc[i][2] + bsh2[tx*4+2]);
            sg.w = sigmoidf_(acc[i][3] + bsh2[tx*4+3]);
            *((float4*)(out_fm + ((size_t)gr * KK + k) * FF + tx * 4)) = sg;
            float4 m = make_float4(xr.x * nmu * sg.x, xr.y * nmu * sg.y,
                                   xr.z * nmu * sg.z, xr.w * nmu * sg.w);
            *((float4*)(g_h0 + ((size_t)gr * KK + k) * HH + tx * 4)) = m;
        }
    }
}

// ---------------- edge mask ----------------
__global__ __launch_bounds__(256) void edge_mask_kernel(
    const float* __restrict__ emb1, const float* __restrict__ emW2,
    const float* __restrict__ emb2, float* __restrict__ out_em)
{
    __shared__ __align__(16) float b1s[64];
    __shared__ __align__(16) float w2s[64];
    int tid = threadIdx.x;
    int k = blockIdx.y;
    if (tid < 64) { b1s[tid] = emb1[k * 64 + tid]; w2s[tid] = emW2[k * 64 + tid]; }
    __syncthreads();
    const float* ABk = g_AB + (size_t)k * NN * 128;
    int idx = blockIdx.x * 256 + tid;
    int p = idx >> 4, lane = idx & 15;
    int s = g_csr_src[p], d = g_csr_dst[p];
    float4 a  = *((const float4*)(ABk + (size_t)s * 128) + lane);
    float4 bb = *((const float4*)(ABk + (size_t)d * 128 + 64) + lane);
    float4 bi = ((const float4*)b1s)[lane];
    float4 w  = ((const float4*)w2s)[lane];
    float pp = fmaxf(a.x + bb.x + bi.x, 0.f) * w.x
             + fmaxf(a.y + bb.y + bi.y, 0.f) * w.y
             + fmaxf(a.z + bb.z + bi.z, 0.f) * w.z
             + fmaxf(a.w + bb.w + bi.w, 0.f) * w.w;
    #pragma unroll
    for (int off = 8; off > 0; off >>= 1)
        pp += __shfl_down_sync(0xffffffffu, pp, off, 16);
    if (lane == 0) {
        float sg = sigmoidf_(pp + emb2[k]);
        g_ewc[(size_t)p * KK + k] = sg;
        out_em[(size_t)g_csr_eid[p] * KK + k] = sg;
    }
}

// ---------------- finalize ----------------
__global__ __launch_bounds__(64) void finalize_kernel(
    const float* __restrict__ clfW, const float* __restrict__ clfb,
    float* __restrict__ out_logits, float* __restrict__ out_hstab,
    float* __restrict__ out_horig)
{
    int b = blockIdx.x, t = threadIdx.x;
    __shared__ float hs[64];
    float inv = 1.0f / fmaxf((float)g_cnt[b], 1.0f);
    out_horig[b * HH + t] = g_poolZ[b * HH + t] * inv;
    for (int k = 0; k < KK; k++) {
        float v = g_poolS[((size_t)k * NB_BATCH + b) * HH + t] * inv;
        out_hstab[((size_t)b * KK + k) * HH + t] = v;
        hs[t] = v;
        __syncthreads();
        if (t < CC) {
            float sacc = clfb[k * CC + t];
            #pragma unroll 8
            for (int h2 = 0; h2 < HH; h2++)
                sacc += hs[h2] * clfW[((size_t)k * HH + h2) * CC + t];
            out_logits[((size_t)b * KK + k) * CC + t] = sacc;
        }
        __syncthreads();
    }
}

// ---------------- host launch ----------------
extern "C" void kernel_launch(void* const* d_in, const int* in_sizes, int n_in,
                              void* d_out, int out_size)
{
    const float* x     = (const float*)d_in[0];
    const int*   ei    = (const int*)d_in[1];
    const int*   batch = (const int*)d_in[2];
    const float* ceW1  = (const float*)d_in[3];
    const float* ceb1  = (const float*)d_in[4];
    const float* ceW2  = (const float*)d_in[5];
    const float* ceb2  = (const float*)d_in[6];
    const float* ceeps = (const float*)d_in[7];
    const float* clW1  = (const float*)d_in[8];
    const float* clb1  = (const float*)d_in[9];
    const float* clW2  = (const float*)d_in[10];
    const float* clb2  = (const float*)d_in[11];
    const float* cleps = (const float*)d_in[12];
    const float* nmW1  = (const float*)d_in[13];
    const float* nmb1  = (const float*)d_in[14];
    const float* nmW2  = (const float*)d_in[15];
    const float* nmb2  = (const float*)d_in[16];
    const float* emW1  = (const float*)d_in[17];
    const float* emb1  = (const float*)d_in[18];
    const float* emW2  = (const float*)d_in[19];
    const float* emb2  = (const float*)d_in[20];
    const float* fmW1  = (const float*)d_in[21];
    const float* fmb1  = (const float*)d_in[22];
    const float* fmW2  = (const float*)d_in[23];
    const float* fmb2  = (const float*)d_in[24];
    const float* clfW  = (const float*)d_in[25];
    const float* clfb  = (const float*)d_in[26];

    const int* src = ei;
    const int* dst = ei + EE;

    float* Z_p;     cudaGetSymbolAddress((void**)&Z_p, g_Z);
    float* h0_p;    cudaGetSymbolAddress((void**)&h0_p, g_h0);
    float* h1_p;    cudaGetSymbolAddress((void**)&h1_p, g_h1);
    float* poolZ_p; cudaGetSymbolAddress((void**)&poolZ_p, g_poolZ);
    float* poolS_p; cudaGetSymbolAddress((void**)&poolS_p, g_poolS);

    float* out        = (float*)d_out;
    float* out_logits = out;
    float* out_hstab  = out_logits + NB_BATCH * KK * CC;
    float* out_horig  = out_hstab + NB_BATCH * KK * HH;
    float* out_nm     = out_horig + NB_BATCH * HH;
    float* out_em     = out_nm + (size_t)NN * KK;
    float* out_fm     = out_em + (size_t)EE * KK;

    const int GB = (NN + 63) / 64;          // 782
    const int GC = NN / 16;                 // 3125
    const int EG = (EE + 255) / 256;        // 3125
    const int EDGE_GRID = (EE * 16) / 256;  // 50000
    const int IG = (KK * NB_BATCH * HH + 255) / 256;

    // ---- CSR build + init ----
    init_kernel<<<IG, 256>>>();
    histcnt_kernel<<<EG, 256>>>(dst, batch);
    scan_kernel<<<1, 1024>>>();
    fill_kernel<<<EG, 256>>>(src, dst);

    // ---- causal encoder GIN (3 layers); layer 3 fuses Z pooling ----
    ginenc_kernel<<<GB, 256>>>(x, h1_p, ceeps, 0, ceW1, ceb1, ceW2, ceb2, nullptr, nullptr);
    ginenc_kernel<<<GB, 256>>>(h1_p, h0_p, ceeps, 1, ceW1 + 4096, ceb1 + 64,
                               ceW2 + 4096, ceb2 + 64, nullptr, nullptr);
    ginenc_kernel<<<GB, 256>>>(h0_p, Z_p, ceeps, 2, ceW1 + 8192, ceb1 + 128,
                               ceW2 + 8192, ceb2 + 128, poolZ_p, batch);

    // ---- masks (writes interleaved g_h0) ----
    mask_kernel<<<dim3(GB, KK), 256>>>(Z_p, x, nmW1, nmb1, nmW2, nmb2,
                                       emW1, fmW1, fmb1, fmW2, fmb2,
                                       out_nm, out_fm);
    edge_mask_kernel<<<dim3(EDGE_GRID, KK), 256>>>(emb1, emW2, emb2, out_em);

    // ---- classifier GIN (3 layers, all K); layer 3 fuses pooling ----
    gincl_kernel<<<GC, 256>>>(h0_p, h1_p, cleps, 0, clW1, clb1, clW2, clb2,
                              nullptr, nullptr);
    gincl_kernel<<<GC, 256>>>(h1_p, h0_p, cleps, 1, clW1 + 4096, clb1 + 64,
                              clW2 + 4096, clb2 + 64, nullptr, nullptr);
    gincl_kernel<<<GC, 256>>>(h0_p, h1_p, cleps, 2, clW1 + 8192, clb1 + 128,
                              clW2 + 8192, clb2 + 128, poolS_p, batch);

    // ---- finalize ----
    finalize_kernel<<<NB_BATCH, 64>>>(clfW, clfb, out_logits, out_hstab, out_horig);
}

// round 13
// speedup vs baseline: 1.0970x; 1.0101x over previous
#include <cuda_runtime.h>
#include <math.h>
#include <stdint.h>

#define NN 50000
#define EE 800000
#define HH 64
#define FF 64
#define CC 10
#define KK 4
#define LL 3
#define NB_BATCH 256
#define SPAD 68
#define WSPAD 72

// ---------------- device scratch ----------------
__device__ float g_Z[NN * HH];
__device__ float g_h0[(size_t)NN * KK * HH];
__device__ float g_h1[(size_t)NN * KK * HH];
__device__ float g_AB[(size_t)KK * NN * 128];
__device__ float g_ewc[(size_t)EE * KK];
__device__ int   g_deg[NN];
__device__ int   g_off[NN + 1];
__device__ int   g_fill[NN];
__device__ int   g_csr_src[EE + 2];   // +2 sentinel for predicate-free prefetch
__device__ int   g_csr_eid[EE];
__device__ float g_poolZ[NB_BATCH * HH];
__device__ float g_poolS[KK * NB_BATCH * HH];
__device__ int   g_cnt[NB_BATCH];

__device__ __forceinline__ void red_add_f4(float4* p, float4 v) {
    asm volatile("red.global.add.v4.f32 [%0], {%1,%2,%3,%4};"
                 :: "l"(p), "f"(v.x), "f"(v.y), "f"(v.z), "f"(v.w) : "memory");
}
__device__ __forceinline__ float sigmoidf_(float v) { return 1.0f / (1.0f + expf(-v)); }

__device__ __forceinline__ uint32_t tf32_rna(float a) {
    uint32_t h; asm("cvt.rna.tf32.f32 %0, %1;" : "=r"(h) : "f"(a)); return h;
}

__device__ __forceinline__ void loadWsplit(const float* __restrict__ W,
                                           float* Wh, float* Wl, int tid) {
    for (int i = tid; i < 1024; i += 256) {
        float4 w = ((const float4*)W)[i];
        int k = i >> 4, j = (i & 15) * 4;
        float4 h, l;
        h.x = __uint_as_float(tf32_rna(w.x)); l.x = __uint_as_float(tf32_rna(w.x - h.x));
        h.y = __uint_as_float(tf32_rna(w.y)); l.y = __uint_as_float(tf32_rna(w.y - h.y));
        h.z = __uint_as_float(tf32_rna(w.z)); l.z = __uint_as_float(tf32_rna(w.z - h.z));
        h.w = __uint_as_float(tf32_rna(w.w)); l.w = __uint_as_float(tf32_rna(w.w - h.w));
        *((float4*)&Wh[k * WSPAD + j]) = h;
        *((float4*)&Wl[k * WSPAD + j]) = l;
    }
}

#define MMA_TF32(c, A0, A1, A2, A3, B0, B1) \
    asm("mma.sync.aligned.m16n8k8.row.col.f32.tf32.tf32.f32 " \
        "{%0,%1,%2,%3}, {%4,%5,%6,%7}, {%8,%9}, {%0,%1,%2,%3};" \
        : "+f"((c)[0]), "+f"((c)[1]), "+f"((c)[2]), "+f"((c)[3]) \
        : "r"(A0), "r"(A1), "r"(A2), "r"(A3), "r"(B0), "r"(B1))

__device__ __forceinline__ void gemm_frag(const float* As, const float* Wh,
                                          const float* Wl, float c[4][4],
                                          int lane, int warp) {
    int mband = (warp & 3) * 16, nhalf = (warp >> 2) * 32;
    int lr = lane >> 2, lc = lane & 3;
    #pragma unroll
    for (int nt = 0; nt < 4; nt++)
        #pragma unroll
        for (int q = 0; q < 4; q++) c[nt][q] = 0.f;
    #pragma unroll
    for (int ks = 0; ks < 8; ks++) {
        int k0 = ks * 8;
        float a0 = As[(mband + lr) * SPAD + k0 + lc];
        float a1 = As[(mband + 8 + lr) * SPAD + k0 + lc];
        float a2 = As[(mband + lr) * SPAD + k0 + 4 + lc];
        float a3 = As[(mband + 8 + lr) * SPAD + k0 + 4 + lc];
        uint32_t ah0 = tf32_rna(a0), ah1 = tf32_rna(a1);
        uint32_t ah2 = tf32_rna(a2), ah3 = tf32_rna(a3);
        uint32_t al0 = tf32_rna(a0 - __uint_as_float(ah0));
        uint32_t al1 = tf32_rna(a1 - __uint_as_float(ah1));
        uint32_t al2 = tf32_rna(a2 - __uint_as_float(ah2));
        uint32_t al3 = tf32_rna(a3 - __uint_as_float(ah3));
        #pragma unroll
        for (int nt = 0; nt < 4; nt++) {
            int n = nhalf + nt * 8 + lr;
            uint32_t bh0 = __float_as_uint(Wh[(k0 + lc) * WSPAD + n]);
            uint32_t bl0 = __float_as_uint(Wl[(k0 + lc) * WSPAD + n]);
            uint32_t bh1 = __float_as_uint(Wh[(k0 + 4 + lc) * WSPAD + n]);
            uint32_t bl1 = __float_as_uint(Wl[(k0 + 4 + lc) * WSPAD + n]);
            MMA_TF32(c[nt], ah0, ah1, ah2, ah3, bh0, bh1);
            MMA_TF32(c[nt], al0, al1, al2, al3, bh0, bh1);
            MMA_TF32(c[nt], ah0, ah1, ah2, ah3, bl0, bl1);
        }
    }
}

__device__ __forceinline__ void stage_frag(const float c[4][4], float* Cs,
                                           int lane, int warp) {
    int mband = (warp & 3) * 16, nhalf = (warp >> 2) * 32;
    int lr = lane >> 2, lc = lane & 3;
    #pragma unroll
    for (int nt = 0; nt < 4; nt++) {
        int col = nhalf + nt * 8 + lc * 2;
        *((float2*)&Cs[(mband + lr) * SPAD + col])     = make_float2(c[nt][0], c[nt][1]);
        *((float2*)&Cs[(mband + 8 + lr) * SPAD + col]) = make_float2(c[nt][2], c[nt][3]);
    }
}

__device__ __forceinline__ void read_acc(const float* Cs, float acc[4][4],
                                         int tx, int ty) {
    #pragma unroll
    for (int i = 0; i < 4; i++) {
        float4 v = *((const float4*)&Cs[(ty * 4 + i) * SPAD + tx * 4]);
        acc[i][0] = v.x; acc[i][1] = v.y; acc[i][2] = v.z; acc[i][3] = v.w;
    }
}

__device__ __forceinline__ void frag_relu_to_As(const float c[4][4], const float* bsh,
                                                float* As, int lane, int warp) {
    int mband = (warp & 3) * 16, nhalf = (warp >> 2) * 32;
    int lr = lane >> 2, lc = lane & 3;
    #pragma unroll
    for (int nt = 0; nt < 4; nt++) {
        int col = nhalf + nt * 8 + lc * 2;
        float b0 = bsh[col], b1 = bsh[col + 1];
        *((float2*)&As[(mband + lr) * SPAD + col]) =
            make_float2(fmaxf(c[nt][0] + b0, 0.f), fmaxf(c[nt][1] + b1, 0.f));
        *((float2*)&As[(mband + 8 + lr) * SPAD + col]) =
            make_float2(fmaxf(c[nt][2] + b0, 0.f), fmaxf(c[nt][3] + b1, 0.f));
    }
}

// ---------------- init ----------------
__global__ __launch_bounds__(256) void init_kernel() {
    int i = blockIdx.x * 256 + threadIdx.x;
    if (i < NN) { g_deg[i] = 0; g_fill[i] = 0; }
    if (i < NB_BATCH) g_cnt[i] = 0;
    if (i < NB_BATCH * HH) g_poolZ[i] = 0.f;
    if (i < KK * NB_BATCH * HH) g_poolS[i] = 0.f;
    if (i < 2) g_csr_src[EE + i] = 0;
}

__global__ __launch_bounds__(256) void histcnt_kernel(const int* __restrict__ dst,
                                                      const int* __restrict__ batch) {
    int e = blockIdx.x * 256 + threadIdx.x;
    if (e < EE) atomicAdd(&g_deg[dst[e]], 1);
    if (e < NN) atomicAdd(&g_cnt[batch[e]], 1);
}

__global__ __launch_bounds__(1024) void scan_kernel() {
    __shared__ int wsum[32];
    __shared__ int carry_s;
    int tid = threadIdx.x, lane = tid & 31, wid = tid >> 5;
    if (tid == 0) carry_s = 0;
    __syncthreads();
    for (int base = 0; base < NN; base += 1024) {
        int v = (base + tid < NN) ? g_deg[base + tid] : 0;
        int inc = v;
        #pragma unroll
        for (int off = 1; off < 32; off <<= 1) {
            int t = __shfl_up_sync(0xffffffffu, inc, off);
            if (lane >= off) inc += t;
        }
        if (lane == 31) wsum[wid] = inc;
        __syncthreads();
        if (wid == 0) {
            int s = wsum[lane];
            #pragma unroll
            for (int off = 1; off < 32; off <<= 1) {
                int t = __shfl_up_sync(0xffffffffu, s, off);
                if (lane >= off) s += t;
            }
            wsum[lane] = s;
        }
        __syncthreads();
        int wpre = wid ? wsum[wid - 1] : 0;
        int excl = carry_s + wpre + inc - v;
        if (base + tid < NN) g_off[base + tid] = excl;
        __syncthreads();
        if (tid == 0) carry_s += wsum[31];
        __syncthreads();
    }
    if (threadIdx.x == 0) g_off[NN] = carry_s;
}

__global__ __launch_bounds__(256) void fill_kernel(const int* __restrict__ src,
                                                   const int* __restrict__ dst) {
    int e = blockIdx.x * 256 + threadIdx.x;
    if (e < EE) {
        int d = dst[e];
        int pos = g_off[d] + atomicAdd(&g_fill[d], 1);
        g_csr_src[pos] = src[e];
        g_csr_eid[pos] = e;
    }
}

// ---------------- encoder GIN layer ----------------
__global__ __launch_bounds__(256) void ginenc_kernel(
    const float* __restrict__ hin, float* __restrict__ hout,
    const float* __restrict__ eps_ptr, int lidx,
    const float* __restrict__ W1, const float* __restrict__ b1,
    const float* __restrict__ W2, const float* __restrict__ b2,
    float* __restrict__ pool, const int* __restrict__ batch)
{
    __shared__ __align__(16) float As[64 * SPAD];
    __shared__ __align__(16) float Wh[64 * WSPAD];
    __shared__ __align__(16) float Wl[64 * WSPAD];
    __shared__ float bsh[64], bsh2[64];
    int tid = threadIdx.x;
    int r0 = blockIdx.x * 64;
    float epsv = 1.0f + eps_ptr[lidx];
    int part = tid & 15, grp = tid >> 4;
    int lane = tid & 31, warp = tid >> 5;

    #pragma unroll
    for (int rr = 0; rr < 4; rr++) {
        int row = rr * 16 + grp;
        int gr = r0 + row;
        float4 a = make_float4(0.f, 0.f, 0.f, 0.f);
        if (gr < NN) {
            float4 h = ((const float4*)(hin + (size_t)gr * HH))[part];
            a.x = epsv * h.x; a.y = epsv * h.y; a.z = epsv * h.z; a.w = epsv * h.w;
            int beg = g_off[gr], end = g_off[gr + 1];
            int p = beg;
            for (; p + 1 < end; p += 2) {
                int s0 = g_csr_src[p], s1 = g_csr_src[p + 1];
                float4 v0 = ((const float4*)(hin + (size_t)s0 * HH))[part];
                float4 v1 = ((const float4*)(hin + (size_t)s1 * HH))[part];
                a.x += v0.x + v1.x; a.y += v0.y + v1.y;
                a.z += v0.z + v1.z; a.w += v0.w + v1.w;
            }
            if (p < end) {
                int s0 = g_csr_src[p];
                float4 v0 = ((const float4*)(hin + (size_t)s0 * HH))[part];
                a.x += v0.x; a.y += v0.y; a.z += v0.z; a.w += v0.w;
            }
        }
        *((float4*)&As[row * SPAD + part * 4]) = a;
    }

    loadWsplit(W1, Wh, Wl, tid);
    if (tid < 64) { bsh[tid] = b1[tid]; bsh2[tid] = b2[tid]; }
    __syncthreads();

    int tx = tid & 15, ty = tid >> 4;
    float c[4][4];
    gemm_frag(As, Wh, Wl, c, lane, warp);
    __syncthreads();
    frag_relu_to_As(c, bsh, As, lane, warp);
    loadWsplit(W2, Wh, Wl, tid);
    __syncthreads();
    gemm_frag(As, Wh, Wl, c, lane, warp);
    __syncthreads();
    stage_frag(c, Wh, lane, warp);
    __syncthreads();
    float acc[4][4];
    read_acc(Wh, acc, tx, ty);
    #pragma unroll
    for (int i = 0; i < 4; i++) {
        int go = r0 + ty * 4 + i;
        if (go < NN) {
            float4 o;
            o.x = fmaxf(acc[i][0] + bsh2[tx*4+0], 0.f);
            o.y = fmaxf(acc[i][1] + bsh2[tx*4+1], 0.f);
            o.z = fmaxf(acc[i][2] + bsh2[tx*4+2], 0.f);
            o.w = fmaxf(acc[i][3] + bsh2[tx*4+3], 0.f);
            *((float4*)(hout + (size_t)go * HH + tx * 4)) = o;
            if (pool) {
                int b = batch[go];
                red_add_f4((float4*)(pool + (size_t)b * HH + tx * 4), o);
            }
        }
    }
}

// ---------------- classifier GIN layer ----------------
__global__ __launch_bounds__(256) void gincl_kernel(
    const float* __restrict__ hin, float* __restrict__ hout,
    const float* __restrict__ eps_ptr, int lidx,
    const float* __restrict__ W1, const float* __restrict__ b1,
    const float* __restrict__ W2, const float* __restrict__ b2,
    float* __restrict__ pool, const int* __restrict__ batch)
{
    __shared__ __align__(16) float As[64 * SPAD];
    __shared__ __align__(16) float Wh[64 * WSPAD];
    __shared__ __align__(16) float Wl[64 * WSPAD];
    __shared__ float bsh[64], bsh2[64];
    int tid = threadIdx.x;
    int n0 = blockIdx.x * 16;
    float epsv = 1.0f + eps_ptr[lidx];
    int part = tid & 15, grp = tid >> 4;
    int lane = tid & 31, warp = tid >> 5;

    {
        int gr = n0 + grp;
        const float4* hbase = (const float4*)(hin + (size_t)gr * KK * HH);
        float4 a[4];
        #pragma unroll
        for (int k = 0; k < 4; k++) {
            float4 h = hbase[k * 16 + part];
            a[k].x = epsv * h.x; a[k].y = epsv * h.y;
            a[k].z = epsv * h.z; a[k].w = epsv * h.w;
        }
        int beg = g_off[gr], end = g_off[gr + 1];
        int s_next = g_csr_src[beg];
        for (int p = beg; p < end; p++) {
            int s = s_next;
            s_next = g_csr_src[p + 1];   // sentinel-padded, always safe
            float4 w4 = *((const float4*)(g_ewc + (size_t)p * 4));
            const float4* vb = (const float4*)(hin + (size_t)s * KK * HH);
            float4 v0 = vb[0 * 16 + part];
            float4 v1 = vb[1 * 16 + part];
            float4 v2 = vb[2 * 16 + part];
            float4 v3 = vb[3 * 16 + part];
            a[0].x = fmaf(w4.x, v0.x, a[0].x); a[0].y = fmaf(w4.x, v0.y, a[0].y);
            a[0].z = fmaf(w4.x, v0.z, a[0].z); a[0].w = fmaf(w4.x, v0.w, a[0].w);
            a[1].x = fmaf(w4.y, v1.x, a[1].x); a[1].y = fmaf(w4.y, v1.y, a[1].y);
            a[1].z = fmaf(w4.y, v1.z, a[1].z); a[1].w = fmaf(w4.y, v1.w, a[1].w);
            a[2].x = fmaf(w4.z, v2.x, a[2].x); a[2].y = fmaf(w4.z, v2.y, a[2].y);
            a[2].z = fmaf(w4.z, v2.z, a[2].z); a[2].w = fmaf(w4.z, v2.w, a[2].w);
            a[3].x = fmaf(w4.w, v3.x, a[3].x); a[3].y = fmaf(w4.w, v3.y, a[3].y);
            a[3].z = fmaf(w4.w, v3.z, a[3].z); a[3].w = fmaf(w4.w, v3.w, a[3].w);
        }
        #pragma unroll
        for (int k = 0; k < 4; k++)
            *((float4*)&As[(grp * 4 + k) * SPAD + part * 4]) = a[k];
    }

    loadWsplit(W1, Wh, Wl, tid);
    if (tid < 64) { bsh[tid] = b1[tid]; bsh2[tid] = b2[tid]; }
    __syncthreads();

    int tx = tid & 15, ty = tid >> 4;
    float c[4][4];
    gemm_frag(As, Wh, Wl, c, lane, warp);
    __syncthreads();
    frag_relu_to_As(c, bsh, As, lane, warp);
    loadWsplit(W2, Wh, Wl, tid);
    __syncthreads();
    gemm_frag(As, Wh, Wl, c, lane, warp);
    __syncthreads();
    stage_frag(c, Wh, lane, warp);
    __syncthreads();
    float acc[4][4];
    read_acc(Wh, acc, tx, ty);
    #pragma unroll
    for (int i = 0; i < 4; i++) {
        int row = ty * 4 + i;
        int gn = n0 + (row >> 2);
        int ke = row & 3;
        float4 o;
        o.x = fmaxf(acc[i][0] + bsh2[tx*4+0], 0.f);
        o.y = fmaxf(acc[i][1] + bsh2[tx*4+1], 0.f);
        o.z = fmaxf(acc[i][2] + bsh2[tx*4+2], 0.f);
        o.w = fmaxf(acc[i][3] + bsh2[tx*4+3], 0.f);
        *((float4*)(hout + ((size_t)gn * KK + ke) * HH + tx * 4)) = o;
        if (pool) {
            int b = batch[gn];
            red_add_f4((float4*)(pool + ((size_t)ke * NB_BATCH + b) * HH + tx * 4), o);
        }
    }
}

// ---------------- fused mask kernel ----------------
__global__ __launch_bounds__(256) void mask_kernel(
    const float* __restrict__ Z, const float* __restrict__ x,
    const float* __restrict__ nmW1, const float* __restrict__ nmb1,
    const float* __restrict__ nmW2, const float* __restrict__ nmb2,
    const float* __restrict__ emW1,
    const float* __restrict__ fmW1, const float* __restrict__ fmb1,
    const float* __restrict__ fmW2, const float* __restrict__ fmb2,
    float* __restrict__ out_nm, float* __restrict__ out_fm)
{
    __shared__ __align__(16) float As[64 * SPAD];
    __shared__ __align__(16) float Wh[64 * WSPAD];
    __shared__ __align__(16) float Wl[64 * WSPAD];
    __shared__ float bsh[64], bsh2[64], w2s[64], nmv[64];
    int tid = threadIdx.x, r0 = blockIdx.x * 64;
    int k = blockIdx.y;
    int lane = tid & 31, warp = tid >> 5;
    const float* nmW1k = nmW1 + (size_t)k * 4096;
    const float* nmb1k = nmb1 + (size_t)k * 64;
    const float* nmW2k = nmW2 + (size_t)k * 64;
    const float* emW1k = emW1 + (size_t)k * 8192;
    const float* fmW1k = fmW1 + (size_t)k * 4096;
    const float* fmb1k = fmb1 + (size_t)k * 64;
    const float* fmW2k = fmW2 + (size_t)k * 4096;
    const float* fmb2k = fmb2 + (size_t)k * 64;
    float* ABk = g_AB + (size_t)k * NN * 128;

    {
        int row = tid >> 2, p0 = (tid & 3) * 4, gr = r0 + row;
        #pragma unroll
        for (int q = 0; q < 4; q++) {
            float4 v = make_float4(0.f, 0.f, 0.f, 0.f);
            if (gr < NN) v = ((const float4*)(Z + (size_t)gr * HH))[p0 + q];
            *((float4*)&As[row * SPAD + (p0 + q) * 4]) = v;
        }
    }
    int tx = tid & 15, ty = tid >> 4;
    float c[4][4], acc[4][4];

    // ---- node mask ----
    loadWsplit(nmW1k, Wh, Wl, tid);
    if (tid < 64) { bsh[tid] = nmb1k[tid]; w2s[tid] = nmW2k[tid]; }
    __syncthreads();
    gemm_frag(As, Wh, Wl, c, lane, warp);
    __syncthreads();
    stage_frag(c, Wh, lane, warp);
    __syncthreads();
    read_acc(Wh, acc, tx, ty);
    float b2v = nmb2[k];
    #pragma unroll
    for (int i = 0; i < 4; i++) {
        float p = 0.f;
        #pragma unroll
        for (int j = 0; j < 4; j++)
            p += fmaxf(acc[i][j] + bsh[tx*4+j], 0.f) * w2s[tx*4+j];
        #pragma unroll
        for (int off = 8; off > 0; off >>= 1)
            p += __shfl_down_sync(0xffffffffu, p, off, 16);
        if (tx == 0) {
            float sg = sigmoidf_(p + b2v);
            nmv[ty * 4 + i] = sg;
            int gr = r0 + ty * 4 + i;
            if (gr < NN) out_nm[(size_t)gr * KK + k] = sg;
        }
    }
    __syncthreads();

    // ---- AB precompute ----
    #pragma unroll
    for (int half = 0; half < 2; half++) {
        loadWsplit(emW1k + half * 4096, Wh, Wl, tid);
        __syncthreads();
        gemm_frag(As, Wh, Wl, c, lane, warp);
        __syncthreads();
        stage_frag(c, Wh, lane, warp);
        __syncthreads();
        read_acc(Wh, acc, tx, ty);
        #pragma unroll
        for (int i = 0; i < 4; i++) {
            int gr = r0 + ty * 4 + i;
            if (gr < NN) {
                float4 o = make_float4(acc[i][0], acc[i][1], acc[i][2], acc[i][3]);
                *((float4*)(ABk + (size_t)gr * 128 + half * 64 + tx * 4)) = o;
            }
        }
        __syncthreads();
    }

    // ---- feature mask + masked_x ----
    loadWsplit(fmW1k, Wh, Wl, tid);
    if (tid < 64) { bsh[tid] = fmb1k[tid]; bsh2[tid] = fmb2k[tid]; }
    __syncthreads();
    gemm_frag(As, Wh, Wl, c, lane, warp);
    __syncthreads();
    frag_relu_to_As(c, bsh, As, lane, warp);
    loadWsplit(fmW2k, Wh, Wl, tid);
    __syncthreads();
    gemm_frag(As, Wh, Wl, c, lane, warp);
    __syncthreads();
    stage_frag(c, Wh, lane, warp);
    __syncthreads();
    read_acc(Wh, acc, tx, ty);
    #pragma unroll
    for (int i = 0; i < 4; i++) {
        int gr = r0 + ty * 4 + i;
        if (gr < NN) {
            float nmu = nmv[ty * 4 + i];
            float4 xr = *((const float4*)(x + (size_t)gr * FF + tx * 4));
            float4 sg;
            sg.x = sigmoidf_(acc[i][0] + bsh2[tx*4+0]);
            sg.y = sigmoidf_(acc[i][1] + bsh2[tx*4+1]);
            sg.z = sigmoidf_(acc[i][2] + bsh2[tx*4+2]);
            sg.w = sigmoidf_(acc[i][3] + bsh2[tx*4+3]);
            *((float4*)(out_fm + ((size_t)gr * KK + k) * FF + tx * 4)) = sg;
            float4 m = make_float4(xr.x * nmu * sg.x, xr.y * nmu * sg.y,
                                   xr.z * nmu * sg.z, xr.w * nmu * sg.w);
            *((float4*)(g_h0 + ((size_t)gr * KK + k) * HH + tx * 4)) = m;
        }
    }
}

// ---------------- edge mask: CSR-row-tiled; B[dst]+b1 in registers per row --------------
// grid (NN/16, K). 16 groups of 16 lanes; group handles one dst row; loops its in-edges
// loading only A[src] (halves AB traffic vs per-edge dual loads).
__global__ __launch_bounds__(256) void edge_mask_kernel(
    const float* __restrict__ emb1, const float* __restrict__ emW2,
    const float* __restrict__ emb2, float* __restrict__ out_em)
{
    __shared__ __align__(16) float b1s[64];
    __shared__ __align__(16) float w2s[64];
    int tid = threadIdx.x;
    int k = blockIdx.y;
    if (tid < 64) { b1s[tid] = emb1[k * 64 + tid]; w2s[tid] = emW2[k * 64 + tid]; }
    __syncthreads();
    int lane = tid & 15, grp = tid >> 4;
    int gr = blockIdx.x * 16 + grp;        // NN % 16 == 0
    const float* ABk = g_AB + (size_t)k * NN * 128;
    float b2v = emb2[k];

    float4 bb = *((const float4*)(ABk + (size_t)gr * 128 + 64) + lane);
    float4 bi = ((const float4*)b1s)[lane];
    bb.x += bi.x; bb.y += bi.y; bb.z += bi.z; bb.w += bi.w;
    float4 w = ((const float4*)w2s)[lane];

    int beg = g_off[gr], end = g_off[gr + 1];
    for (int p = beg; p < end; p++) {
        int s = g_csr_src[p];
        float4 a = *((const float4*)(ABk + (size_t)s * 128) + lane);
        float pp = fmaxf(a.x + bb.x, 0.f) * w.x
                 + fmaxf(a.y + bb.y, 0.f) * w.y
                 + fmaxf(a.z + bb.z, 0.f) * w.z
                 + fmaxf(a.w + bb.w, 0.f) * w.w;
        #pragma unroll
        for (int off = 8; off > 0; off >>= 1)
            pp += __shfl_down_sync(0xffffffffu, pp, off, 16);
        if (lane == 0) {
            float sg = sigmoidf_(pp + b2v);
            g_ewc[(size_t)p * KK + k] = sg;
            out_em[(size_t)g_csr_eid[p] * KK + k] = sg;
        }
    }
}

// ---------------- finalize ----------------
__global__ __launch_bounds__(64) void finalize_kernel(
    const float* __restrict__ clfW, const float* __restrict__ clfb,
    float* __restrict__ out_logits, float* __restrict__ out_hstab,
    float* __restrict__ out_horig)
{
    int b = blockIdx.x, t = threadIdx.x;
    __shared__ float hs[64];
    float inv = 1.0f / fmaxf((float)g_cnt[b], 1.0f);
    out_horig[b * HH + t] = g_poolZ[b * HH + t] * inv;
    for (int k = 0; k < KK; k++) {
        float v = g_poolS[((size_t)k * NB_BATCH + b) * HH + t] * inv;
        out_hstab[((size_t)b * KK + k) * HH + t] = v;
        hs[t] = v;
        __syncthreads();
        if (t < CC) {
            float sacc = clfb[k * CC + t];
            #pragma unroll 8
            for (int h2 = 0; h2 < HH; h2++)
                sacc += hs[h2] * clfW[((size_t)k * HH + h2) * CC + t];
            out_logits[((size_t)b * KK + k) * CC + t] = sacc;
        }
        __syncthreads();
    }
}

// ---------------- host launch ----------------
extern "C" void kernel_launch(void* const* d_in, const int* in_sizes, int n_in,
                              void* d_out, int out_size)
{
    const float* x     = (const float*)d_in[0];
    const int*   ei    = (const int*)d_in[1];
    const int*   batch = (const int*)d_in[2];
    const float* ceW1  = (const float*)d_in[3];
    const float* ceb1  = (const float*)d_in[4];
    const float* ceW2  = (const float*)d_in[5];
    const float* ceb2  = (const float*)d_in[6];
    const float* ceeps = (const float*)d_in[7];
    const float* clW1  = (const float*)d_in[8];
    const float* clb1  = (const float*)d_in[9];
    const float* clW2  = (const float*)d_in[10];
    const float* clb2  = (const float*)d_in[11];
    const float* cleps = (const float*)d_in[12];
    const float* nmW1  = (const float*)d_in[13];
    const float* nmb1  = (const float*)d_in[14];
    const float* nmW2  = (const float*)d_in[15];
    const float* nmb2  = (const float*)d_in[16];
    const float* emW1  = (const float*)d_in[17];
    const float* emb1  = (const float*)d_in[18];
    const float* emW2  = (const float*)d_in[19];
    const float* emb2  = (const float*)d_in[20];
    const float* fmW1  = (const float*)d_in[21];
    const float* fmb1  = (const float*)d_in[22];
    const float* fmW2  = (const float*)d_in[23];
    const float* fmb2  = (const float*)d_in[24];
    const float* clfW  = (const float*)d_in[25];
    const float* clfb  = (const float*)d_in[26];

    const int* src = ei;
    const int* dst = ei + EE;

    float* Z_p;     cudaGetSymbolAddress((void**)&Z_p, g_Z);
    float* h0_p;    cudaGetSymbolAddress((void**)&h0_p, g_h0);
    float* h1_p;    cudaGetSymbolAddress((void**)&h1_p, g_h1);
    float* poolZ_p; cudaGetSymbolAddress((void**)&poolZ_p, g_poolZ);
    float* poolS_p; cudaGetSymbolAddress((void**)&poolS_p, g_poolS);

    float* out        = (float*)d_out;
    float* out_logits = out;
    float* out_hstab  = out_logits + NB_BATCH * KK * CC;
    float* out_horig  = out_hstab + NB_BATCH * KK * HH;
    float* out_nm     = out_horig + NB_BATCH * HH;
    float* out_em     = out_nm + (size_t)NN * KK;
    float* out_fm     = out_em + (size_t)EE * KK;

    const int GB = (NN + 63) / 64;          // 782
    const int GC = NN / 16;                 // 3125
    const int EG = (EE + 255) / 256;        // 3125
    const int EM_GRID = NN / 16;            // 3125
    const int IG = (KK * NB_BATCH * HH + 255) / 256;

    // ---- CSR build + init ----
    init_kernel<<<IG, 256>>>();
    histcnt_kernel<<<EG, 256>>>(dst, batch);
    scan_kernel<<<1, 1024>>>();
    fill_kernel<<<EG, 256>>>(src, dst);

    // ---- causal encoder GIN (3 layers); layer 3 fuses Z pooling ----
    ginenc_kernel<<<GB, 256>>>(x, h1_p, ceeps, 0, ceW1, ceb1, ceW2, ceb2, nullptr, nullptr);
    ginenc_kernel<<<GB, 256>>>(h1_p, h0_p, ceeps, 1, ceW1 + 4096, ceb1 + 64,
                               ceW2 + 4096, ceb2 + 64, nullptr, nullptr);
    ginenc_kernel<<<GB, 256>>>(h0_p, Z_p, ceeps, 2, ceW1 + 8192, ceb1 + 128,
                               ceW2 + 8192, ceb2 + 128, poolZ_p, batch);

    // ---- masks (writes interleaved g_h0) ----
    mask_kernel<<<dim3(GB, KK), 256>>>(Z_p, x, nmW1, nmb1, nmW2, nmb2,
                                       emW1, fmW1, fmb1, fmW2, fmb2,
                                       out_nm, out_fm);
    edge_mask_kernel<<<dim3(EM_GRID, KK), 256>>>(emb1, emW2, emb2, out_em);

    // ---- classifier GIN (3 layers, all K); layer 3 fuses pooling ----
    gincl_kernel<<<GC, 256>>>(h0_p, h1_p, cleps, 0, clW1, clb1, clW2, clb2,
                              nullptr, nullptr);
    gincl_kernel<<<GC, 256>>>(h1_p, h0_p, cleps, 1, clW1 + 4096, clb1 + 64,
                              clW2 + 4096, clb2 + 64, nullptr, nullptr);
    gincl_kernel<<<GC, 256>>>(h0_p, h1_p, cleps, 2, clW1 + 8192, clb1 + 128,
                              clW2 + 8192, clb2 + 128, poolS_p, batch);

    // ---- finalize ----
    finalize_kernel<<<NB_BATCH, 64>>>(clfW, clfb, out_logits, out_hstab, out_horig);
}

// round 14
// speedup vs baseline: 1.2053x; 1.0987x over previous
#include <cuda_runtime.h>
#include <math.h>
#include <stdint.h>

#define NN 50000
#define EE 800000
#define HH 64
#define FF 64
#define CC 10
#define KK 4
#define LL 3
#define NB_BATCH 256
#define SPAD 68
#define WSPAD 72

// ---------------- device scratch ----------------
__device__ float g_Z[NN * HH];
__device__ float g_h0[(size_t)NN * KK * HH];
__device__ float g_h1[(size_t)NN * KK * HH];
__device__ float g_AB[(size_t)KK * NN * 128];
__device__ float g_ewc[(size_t)EE * KK];
__device__ int   g_deg[NN];
__device__ int   g_off[NN + 1];
__device__ int   g_fill[NN];
__device__ int   g_csr_src[EE + 4];   // +4 sentinel for predicate-free 2-ahead prefetch
__device__ int   g_csr_eid[EE];
__device__ float g_poolZ[NB_BATCH * HH];
__device__ float g_poolS[KK * NB_BATCH * HH];
__device__ int   g_cnt[NB_BATCH];

__device__ __forceinline__ void red_add_f4(float4* p, float4 v) {
    asm volatile("red.global.add.v4.f32 [%0], {%1,%2,%3,%4};"
                 :: "l"(p), "f"(v.x), "f"(v.y), "f"(v.z), "f"(v.w) : "memory");
}
__device__ __forceinline__ float sigmoidf_(float v) { return 1.0f / (1.0f + expf(-v)); }

__device__ __forceinline__ uint32_t tf32_rna(float a) {
    uint32_t h; asm("cvt.rna.tf32.f32 %0, %1;" : "=r"(h) : "f"(a)); return h;
}

__device__ __forceinline__ void loadWsplit(const float* __restrict__ W,
                                           float* Wh, float* Wl, int tid) {
    for (int i = tid; i < 1024; i += 256) {
        float4 w = ((const float4*)W)[i];
        int k = i >> 4, j = (i & 15) * 4;
        float4 h, l;
        h.x = __uint_as_float(tf32_rna(w.x)); l.x = __uint_as_float(tf32_rna(w.x - h.x));
        h.y = __uint_as_float(tf32_rna(w.y)); l.y = __uint_as_float(tf32_rna(w.y - h.y));
        h.z = __uint_as_float(tf32_rna(w.z)); l.z = __uint_as_float(tf32_rna(w.z - h.z));
        h.w = __uint_as_float(tf32_rna(w.w)); l.w = __uint_as_float(tf32_rna(w.w - h.w));
        *((float4*)&Wh[k * WSPAD + j]) = h;
        *((float4*)&Wl[k * WSPAD + j]) = l;
    }
}

#define MMA_TF32(c, A0, A1, A2, A3, B0, B1) \
    asm("mma.sync.aligned.m16n8k8.row.col.f32.tf32.tf32.f32 " \
        "{%0,%1,%2,%3}, {%4,%5,%6,%7}, {%8,%9}, {%0,%1,%2,%3};" \
        : "+f"((c)[0]), "+f"((c)[1]), "+f"((c)[2]), "+f"((c)[3]) \
        : "r"(A0), "r"(A1), "r"(A2), "r"(A3), "r"(B0), "r"(B1))

__device__ __forceinline__ void gemm_frag(const float* As, const float* Wh,
                                          const float* Wl, float c[4][4],
                                          int lane, int warp) {
    int mband = (warp & 3) * 16, nhalf = (warp >> 2) * 32;
    int lr = lane >> 2, lc = lane & 3;
    #pragma unroll
    for (int nt = 0; nt < 4; nt++)
        #pragma unroll
        for (int q = 0; q < 4; q++) c[nt][q] = 0.f;
    #pragma unroll
    for (int ks = 0; ks < 8; ks++) {
        int k0 = ks * 8;
        float a0 = As[(mband + lr) * SPAD + k0 + lc];
        float a1 = As[(mband + 8 + lr) * SPAD + k0 + lc];
        float a2 = As[(mband + lr) * SPAD + k0 + 4 + lc];
        float a3 = As[(mband + 8 + lr) * SPAD + k0 + 4 + lc];
        uint32_t ah0 = tf32_rna(a0), ah1 = tf32_rna(a1);
        uint32_t ah2 = tf32_rna(a2), ah3 = tf32_rna(a3);
        uint32_t al0 = tf32_rna(a0 - __uint_as_float(ah0));
        uint32_t al1 = tf32_rna(a1 - __uint_as_float(ah1));
        uint32_t al2 = tf32_rna(a2 - __uint_as_float(ah2));
        uint32_t al3 = tf32_rna(a3 - __uint_as_float(ah3));
        #pragma unroll
        for (int nt = 0; nt < 4; nt++) {
            int n = nhalf + nt * 8 + lr;
            uint32_t bh0 = __float_as_uint(Wh[(k0 + lc) * WSPAD + n]);
            uint32_t bl0 = __float_as_uint(Wl[(k0 + lc) * WSPAD + n]);
            uint32_t bh1 = __float_as_uint(Wh[(k0 + 4 + lc) * WSPAD + n]);
            uint32_t bl1 = __float_as_uint(Wl[(k0 + 4 + lc) * WSPAD + n]);
            MMA_TF32(c[nt], ah0, ah1, ah2, ah3, bh0, bh1);
            MMA_TF32(c[nt], al0, al1, al2, al3, bh0, bh1);
            MMA_TF32(c[nt], ah0, ah1, ah2, ah3, bl0, bl1);
        }
    }
}

__device__ __forceinline__ void stage_frag(const float c[4][4], float* Cs,
                                           int lane, int warp) {
    int mband = (warp & 3) * 16, nhalf = (warp >> 2) * 32;
    int lr = lane >> 2, lc = lane & 3;
    #pragma unroll
    for (int nt = 0; nt < 4; nt++) {
        int col = nhalf + nt * 8 + lc * 2;
        *((float2*)&Cs[(mband + lr) * SPAD + col])     = make_float2(c[nt][0], c[nt][1]);
        *((float2*)&Cs[(mband + 8 + lr) * SPAD + col]) = make_float2(c[nt][2], c[nt][3]);
    }
}

__device__ __forceinline__ void read_acc(const float* Cs, float acc[4][4],
                                         int tx, int ty) {
    #pragma unroll
    for (int i = 0; i < 4; i++) {
        float4 v = *((const float4*)&Cs[(ty * 4 + i) * SPAD + tx * 4]);
        acc[i][0] = v.x; acc[i][1] = v.y; acc[i][2] = v.z; acc[i][3] = v.w;
    }
}

__device__ __forceinline__ void frag_relu_to_As(const float c[4][4], const float* bsh,
                                                float* As, int lane, int warp) {
    int mband = (warp & 3) * 16, nhalf = (warp >> 2) * 32;
    int lr = lane >> 2, lc = lane & 3;
    #pragma unroll
    for (int nt = 0; nt < 4; nt++) {
        int col = nhalf + nt * 8 + lc * 2;
        float b0 = bsh[col], b1 = bsh[col + 1];
        *((float2*)&As[(mband + lr) * SPAD + col]) =
            make_float2(fmaxf(c[nt][0] + b0, 0.f), fmaxf(c[nt][1] + b1, 0.f));
        *((float2*)&As[(mband + 8 + lr) * SPAD + col]) =
            make_float2(fmaxf(c[nt][2] + b0, 0.f), fmaxf(c[nt][3] + b1, 0.f));
    }
}

// ---------------- init ----------------
__global__ __launch_bounds__(256) void init_kernel() {
    int i = blockIdx.x * 256 + threadIdx.x;
    if (i < NN) { g_deg[i] = 0; g_fill[i] = 0; }
    if (i < NB_BATCH) g_cnt[i] = 0;
    if (i < NB_BATCH * HH) g_poolZ[i] = 0.f;
    if (i < KK * NB_BATCH * HH) g_poolS[i] = 0.f;
    if (i < 4) g_csr_src[EE + i] = 0;
}

__global__ __launch_bounds__(256) void histcnt_kernel(const int* __restrict__ dst,
                                                      const int* __restrict__ batch) {
    int e = blockIdx.x * 256 + threadIdx.x;
    if (e < EE) atomicAdd(&g_deg[dst[e]], 1);
    if (e < NN) atomicAdd(&g_cnt[batch[e]], 1);
}

__global__ __launch_bounds__(1024) void scan_kernel() {
    __shared__ int wsum[32];
    __shared__ int carry_s;
    int tid = threadIdx.x, lane = tid & 31, wid = tid >> 5;
    if (tid == 0) carry_s = 0;
    __syncthreads();
    for (int base = 0; base < NN; base += 1024) {
        int v = (base + tid < NN) ? g_deg[base + tid] : 0;
        int inc = v;
        #pragma unroll
        for (int off = 1; off < 32; off <<= 1) {
            int t = __shfl_up_sync(0xffffffffu, inc, off);
            if (lane >= off) inc += t;
        }
        if (lane == 31) wsum[wid] = inc;
        __syncthreads();
        if (wid == 0) {
            int s = wsum[lane];
            #pragma unroll
            for (int off = 1; off < 32; off <<= 1) {
                int t = __shfl_up_sync(0xffffffffu, s, off);
                if (lane >= off) s += t;
            }
            wsum[lane] = s;
        }
        __syncthreads();
        int wpre = wid ? wsum[wid - 1] : 0;
        int excl = carry_s + wpre + inc - v;
        if (base + tid < NN) g_off[base + tid] = excl;
        __syncthreads();
        if (tid == 0) carry_s += wsum[31];
        __syncthreads();
    }
    if (threadIdx.x == 0) g_off[NN] = carry_s;
}

__global__ __launch_bounds__(256) void fill_kernel(const int* __restrict__ src,
                                                   const int* __restrict__ dst) {
    int e = blockIdx.x * 256 + threadIdx.x;
    if (e < EE) {
        int d = dst[e];
        int pos = g_off[d] + atomicAdd(&g_fill[d], 1);
        g_csr_src[pos] = src[e];
        g_csr_eid[pos] = e;
    }
}

// ---------------- encoder GIN layer ----------------
__global__ __launch_bounds__(256) void ginenc_kernel(
    const float* __restrict__ hin, float* __restrict__ hout,
    const float* __restrict__ eps_ptr, int lidx,
    const float* __restrict__ W1, const float* __restrict__ b1,
    const float* __restrict__ W2, const float* __restrict__ b2,
    float* __restrict__ pool, const int* __restrict__ batch)
{
    __shared__ __align__(16) float As[64 * SPAD];
    __shared__ __align__(16) float Wh[64 * WSPAD];
    __shared__ __align__(16) float Wl[64 * WSPAD];
    __shared__ float bsh[64], bsh2[64];
    int tid = threadIdx.x;
    int r0 = blockIdx.x * 64;
    float epsv = 1.0f + eps_ptr[lidx];
    int part = tid & 15, grp = tid >> 4;
    int lane = tid & 31, warp = tid >> 5;

    #pragma unroll
    for (int rr = 0; rr < 4; rr++) {
        int row = rr * 16 + grp;
        int gr = r0 + row;
        float4 a = make_float4(0.f, 0.f, 0.f, 0.f);
        if (gr < NN) {
            float4 h = ((const float4*)(hin + (size_t)gr * HH))[part];
            a.x = epsv * h.x; a.y = epsv * h.y; a.z = epsv * h.z; a.w = epsv * h.w;
            int beg = g_off[gr], end = g_off[gr + 1];
            int p = beg;
            int sA = g_csr_src[p], sB = g_csr_src[p + 1];
            for (; p + 1 < end; p += 2) {
                int s0 = sA, s1 = sB;
                sA = g_csr_src[p + 2]; sB = g_csr_src[p + 3];   // sentinel-safe
                float4 v0 = ((const float4*)(hin + (size_t)s0 * HH))[part];
                float4 v1 = ((const float4*)(hin + (size_t)s1 * HH))[part];
                a.x += v0.x + v1.x; a.y += v0.y + v1.y;
                a.z += v0.z + v1.z; a.w += v0.w + v1.w;
            }
            if (p < end) {
                float4 v0 = ((const float4*)(hin + (size_t)sA * HH))[part];
                a.x += v0.x; a.y += v0.y; a.z += v0.z; a.w += v0.w;
            }
        }
        *((float4*)&As[row * SPAD + part * 4]) = a;
    }

    loadWsplit(W1, Wh, Wl, tid);
    if (tid < 64) { bsh[tid] = b1[tid]; bsh2[tid] = b2[tid]; }
    __syncthreads();

    int tx = tid & 15, ty = tid >> 4;
    float c[4][4];
    gemm_frag(As, Wh, Wl, c, lane, warp);
    __syncthreads();
    frag_relu_to_As(c, bsh, As, lane, warp);
    loadWsplit(W2, Wh, Wl, tid);
    __syncthreads();
    gemm_frag(As, Wh, Wl, c, lane, warp);
    __syncthreads();
    stage_frag(c, Wh, lane, warp);
    __syncthreads();
    float acc[4][4];
    read_acc(Wh, acc, tx, ty);
    #pragma unroll
    for (int i = 0; i < 4; i++) {
        int go = r0 + ty * 4 + i;
        if (go < NN) {
            float4 o;
            o.x = fmaxf(acc[i][0] + bsh2[tx*4+0], 0.f);
            o.y = fmaxf(acc[i][1] + bsh2[tx*4+1], 0.f);
            o.z = fmaxf(acc[i][2] + bsh2[tx*4+2], 0.f);
            o.w = fmaxf(acc[i][3] + bsh2[tx*4+3], 0.f);
            *((float4*)(hout + (size_t)go * HH + tx * 4)) = o;
            if (pool) {
                int b = batch[go];
                red_add_f4((float4*)(pool + (size_t)b * HH + tx * 4), o);
            }
        }
    }
}

// ---------------- classifier GIN layer, all K experts, interleaved [n][k][64] ----------
__global__ __launch_bounds__(256) void gincl_kernel(
    const float* __restrict__ hin, float* __restrict__ hout,
    const float* __restrict__ eps_ptr, int lidx,
    const float* __restrict__ W1, const float* __restrict__ b1,
    const float* __restrict__ W2, const float* __restrict__ b2,
    float* __restrict__ pool, const int* __restrict__ batch)
{
    __shared__ __align__(16) float As[64 * SPAD];
    __shared__ __align__(16) float Wh[64 * WSPAD];
    __shared__ __align__(16) float Wl[64 * WSPAD];
    __shared__ float bsh[64], bsh2[64];
    int tid = threadIdx.x;
    int n0 = blockIdx.x * 16;
    float epsv = 1.0f + eps_ptr[lidx];
    int part = tid & 15, grp = tid >> 4;
    int lane = tid & 31, warp = tid >> 5;

    {
        int gr = n0 + grp;
        const float4* hbase = (const float4*)(hin + (size_t)gr * KK * HH);
        float4 a[4];
        #pragma unroll
        for (int k = 0; k < 4; k++) {
            float4 h = hbase[k * 16 + part];
            a[k].x = epsv * h.x; a[k].y = epsv * h.y;
            a[k].z = epsv * h.z; a[k].w = epsv * h.w;
        }
        int beg = g_off[gr], end = g_off[gr + 1];
        int p = beg;
        int sA = g_csr_src[p], sB = g_csr_src[p + 1];
        // 2-edge unrolled, predicate-free 2-ahead index prefetch
        for (; p + 1 < end; p += 2) {
            int s0 = sA, s1 = sB;
            sA = g_csr_src[p + 2]; sB = g_csr_src[p + 3];   // sentinel-safe
            float4 w0 = *((const float4*)(g_ewc + (size_t)p * 4));
            float4 w1 = *((const float4*)(g_ewc + (size_t)(p + 1) * 4));
            const float4* vb0 = (const float4*)(hin + (size_t)s0 * KK * HH);
            const float4* vb1 = (const float4*)(hin + (size_t)s1 * KK * HH);
            float4 v0 = vb0[0 * 16 + part];
            float4 v1 = vb0[1 * 16 + part];
            float4 v2 = vb0[2 * 16 + part];
            float4 v3 = vb0[3 * 16 + part];
            float4 u0 = vb1[0 * 16 + part];
            float4 u1 = vb1[1 * 16 + part];
            float4 u2 = vb1[2 * 16 + part];
            float4 u3 = vb1[3 * 16 + part];
            a[0].x = fmaf(w0.x, v0.x, a[0].x); a[0].y = fmaf(w0.x, v0.y, a[0].y);
            a[0].z = fmaf(w0.x, v0.z, a[0].z); a[0].w = fmaf(w0.x, v0.w, a[0].w);
            a[1].x = fmaf(w0.y, v1.x, a[1].x); a[1].y = fmaf(w0.y, v1.y, a[1].y);
            a[1].z = fmaf(w0.y, v1.z, a[1].z); a[1].w = fmaf(w0.y, v1.w, a[1].w);
            a[2].x = fmaf(w0.z, v2.x, a[2].x); a[2].y = fmaf(w0.z, v2.y, a[2].y);
            a[2].z = fmaf(w0.z, v2.z, a[2].z); a[2].w = fmaf(w0.z, v2.w, a[2].w);
            a[3].x = fmaf(w0.w, v3.x, a[3].x); a[3].y = fmaf(w0.w, v3.y, a[3].y);
            a[3].z = fmaf(w0.w, v3.z, a[3].z); a[3].w = fmaf(w0.w, v3.w, a[3].w);
            a[0].x = fmaf(w1.x, u0.x, a[0].x); a[0].y = fmaf(w1.x, u0.y, a[0].y);
            a[0].z = fmaf(w1.x, u0.z, a[0].z); a[0].w = fmaf(w1.x, u0.w, a[0].w);
            a[1].x = fmaf(w1.y, u1.x, a[1].x); a[1].y = fmaf(w1.y, u1.y, a[1].y);
            a[1].z = fmaf(w1.y, u1.z, a[1].z); a[1].w = fmaf(w1.y, u1.w, a[1].w);
            a[2].x = fmaf(w1.z, u2.x, a[2].x); a[2].y = fmaf(w1.z, u2.y, a[2].y);
            a[2].z = fmaf(w1.z, u2.z, a[2].z); a[2].w = fmaf(w1.z, u2.w, a[2].w);
            a[3].x = fmaf(w1.w, u3.x, a[3].x); a[3].y = fmaf(w1.w, u3.y, a[3].y);
            a[3].z = fmaf(w1.w, u3.z, a[3].z); a[3].w = fmaf(w1.w, u3.w, a[3].w);
        }
        if (p < end) {
            float4 w0 = *((const float4*)(g_ewc + (size_t)p * 4));
            const float4* vb = (const float4*)(hin + (size_t)sA * KK * HH);
            float4 v0 = vb[0 * 16 + part];
            float4 v1 = vb[1 * 16 + part];
            float4 v2 = vb[2 * 16 + part];
            float4 v3 = vb[3 * 16 + part];
            a[0].x = fmaf(w0.x, v0.x, a[0].x); a[0].y = fmaf(w0.x, v0.y, a[0].y);
            a[0].z = fmaf(w0.x, v0.z, a[0].z); a[0].w = fmaf(w0.x, v0.w, a[0].w);
            a[1].x = fmaf(w0.y, v1.x, a[1].x); a[1].y = fmaf(w0.y, v1.y, a[1].y);
            a[1].z = fmaf(w0.y, v1.z, a[1].z); a[1].w = fmaf(w0.y, v1.w, a[1].w);
            a[2].x = fmaf(w0.z, v2.x, a[2].x); a[2].y = fmaf(w0.z, v2.y, a[2].y);
            a[2].z = fmaf(w0.z, v2.z, a[2].z); a[2].w = fmaf(w0.z, v2.w, a[2].w);
            a[3].x = fmaf(w0.w, v3.x, a[3].x); a[3].y = fmaf(w0.w, v3.y, a[3].y);
            a[3].z = fmaf(w0.w, v3.z, a[3].z); a[3].w = fmaf(w0.w, v3.w, a[3].w);
        }
        #pragma unroll
        for (int k = 0; k < 4; k++)
            *((float4*)&As[(grp * 4 + k) * SPAD + part * 4]) = a[k];
    }

    loadWsplit(W1, Wh, Wl, tid);
    if (tid < 64) { bsh[tid] = b1[tid]; bsh2[tid] = b2[tid]; }
    __syncthreads();

    int tx = tid & 15, ty = tid >> 4;
    float c[4][4];
    gemm_frag(As, Wh, Wl, c, lane, warp);
    __syncthreads();
    frag_relu_to_As(c, bsh, As, lane, warp);
    loadWsplit(W2, Wh, Wl, tid);
    __syncthreads();
    gemm_frag(As, Wh, Wl, c, lane, warp);
    __syncthreads();
    stage_frag(c, Wh, lane, warp);
    __syncthreads();
    float acc[4][4];
    read_acc(Wh, acc, tx, ty);
    #pragma unroll
    for (int i = 0; i < 4; i++) {
        int row = ty * 4 + i;
        int gn = n0 + (row >> 2);
        int ke = row & 3;
        float4 o;
        o.x = fmaxf(acc[i][0] + bsh2[tx*4+0], 0.f);
        o.y = fmaxf(acc[i][1] + bsh2[tx*4+1], 0.f);
        o.z = fmaxf(acc[i][2] + bsh2[tx*4+2], 0.f);
        o.w = fmaxf(acc[i][3] + bsh2[tx*4+3], 0.f);
        *((float4*)(hout + ((size_t)gn * KK + ke) * HH + tx * 4)) = o;
        if (pool) {
            int b = batch[gn];
            red_add_f4((float4*)(pool + ((size_t)ke * NB_BATCH + b) * HH + tx * 4), o);
        }
    }
}

// ---------------- fused mask kernel ----------------
__global__ __launch_bounds__(256) void mask_kernel(
    const float* __restrict__ Z, const float* __restrict__ x,
    const float* __restrict__ nmW1, const float* __restrict__ nmb1,
    const float* __restrict__ nmW2, const float* __restrict__ nmb2,
    const float* __restrict__ emW1,
    const float* __restrict__ fmW1, const float* __restrict__ fmb1,
    const float* __restrict__ fmW2, const float* __restrict__ fmb2,
    float* __restrict__ out_nm, float* __restrict__ out_fm)
{
    __shared__ __align__(16) float As[64 * SPAD];
    __shared__ __align__(16) float Wh[64 * WSPAD];
    __shared__ __align__(16) float Wl[64 * WSPAD];
    __shared__ float bsh[64], bsh2[64], w2s[64], nmv[64];
    int tid = threadIdx.x, r0 = blockIdx.x * 64;
    int k = blockIdx.y;
    int lane = tid & 31, warp = tid >> 5;
    const float* nmW1k = nmW1 + (size_t)k * 4096;
    const float* nmb1k = nmb1 + (size_t)k * 64;
    const float* nmW2k = nmW2 + (size_t)k * 64;
    const float* emW1k = emW1 + (size_t)k * 8192;
    const float* fmW1k = fmW1 + (size_t)k * 4096;
    const float* fmb1k = fmb1 + (size_t)k * 64;
    const float* fmW2k = fmW2 + (size_t)k * 4096;
    const float* fmb2k = fmb2 + (size_t)k * 64;
    float* ABk = g_AB + (size_t)k * NN * 128;

    {
        int row = tid >> 2, p0 = (tid & 3) * 4, gr = r0 + row;
        #pragma unroll
        for (int q = 0; q < 4; q++) {
            float4 v = make_float4(0.f, 0.f, 0.f, 0.f);
            if (gr < NN) v = ((const float4*)(Z + (size_t)gr * HH))[p0 + q];
            *((float4*)&As[row * SPAD + (p0 + q) * 4]) = v;
        }
    }
    int tx = tid & 15, ty = tid >> 4;
    float c[4][4], acc[4][4];

    // ---- node mask ----
    loadWsplit(nmW1k, Wh, Wl, tid);
    if (tid < 64) { bsh[tid] = nmb1k[tid]; w2s[tid] = nmW2k[tid]; }
    __syncthreads();
    gemm_frag(As, Wh, Wl, c, lane, warp);
    __syncthreads();
    stage_frag(c, Wh, lane, warp);
    __syncthreads();
    read_acc(Wh, acc, tx, ty);
    float b2v = nmb2[k];
    #pragma unroll
    for (int i = 0; i < 4; i++) {
        float p = 0.f;
        #pragma unroll
        for (int j = 0; j < 4; j++)
            p += fmaxf(acc[i][j] + bsh[tx*4+j], 0.f) * w2s[tx*4+j];
        #pragma unroll
        for (int off = 8; off > 0; off >>= 1)
            p += __shfl_down_sync(0xffffffffu, p, off, 16);
        if (tx == 0) {
            float sg = sigmoidf_(p + b2v);
            nmv[ty * 4 + i] = sg;
            int gr = r0 + ty * 4 + i;
            if (gr < NN) out_nm[(size_t)gr * KK + k] = sg;
        }
    }
    __syncthreads();

    // ---- AB precompute ----
    #pragma unroll
    for (int half = 0; half < 2; half++) {
        loadWsplit(emW1k + half * 4096, Wh, Wl, tid);
        __syncthreads();
        gemm_frag(As, Wh, Wl, c, lane, warp);
        __syncthreads();
        stage_frag(c, Wh, lane, warp);
        __syncthreads();
        read_acc(Wh, acc, tx, ty);
        #pragma unroll
        for (int i = 0; i < 4; i++) {
            int gr = r0 + ty * 4 + i;
            if (gr < NN) {
                float4 o = make_float4(acc[i][0], acc[i][1], acc[i][2], acc[i][3]);
                *((float4*)(ABk + (size_t)gr * 128 + half * 64 + tx * 4)) = o;
            }
        }
        __syncthreads();
    }

    // ---- feature mask + masked_x ----
    loadWsplit(fmW1k, Wh, Wl, tid);
    if (tid < 64) { bsh[tid] = fmb1k[tid]; bsh2[tid] = fmb2k[tid]; }
    __syncthreads();
    gemm_frag(As, Wh, Wl, c, lane, warp);
    __syncthreads();
    frag_relu_to_As(c, bsh, As, lane, warp);
    loadWsplit(fmW2k, Wh, Wl, tid);
    __syncthreads();
    gemm_frag(As, Wh, Wl, c, lane, warp);
    __syncthreads();
    stage_frag(c, Wh, lane, warp);
    __syncthreads();
    read_acc(Wh, acc, tx, ty);
    #pragma unroll
    for (int i = 0; i < 4; i++) {
        int gr = r0 + ty * 4 + i;
        if (gr < NN) {
            float nmu = nmv[ty * 4 + i];
            float4 xr = *((const float4*)(x + (size_t)gr * FF + tx * 4));
            float4 sg;
            sg.x = sigmoidf_(acc[i][0] + bsh2[tx*4+0]);
            sg.y = sigmoidf_(acc[i][1] + bsh2[tx*4+1]);
            sg.z = sigmoidf_(acc[i][2] + bsh2[tx*4+2]);
            sg.w = sigmoidf_(acc[i][3] + bsh2[tx*4+3]);
            *((float4*)(out_fm + ((size_t)gr * KK + k) * FF + tx * 4)) = sg;
            float4 m = make_float4(xr.x * nmu * sg.x, xr.y * nmu * sg.y,
                                   xr.z * nmu * sg.z, xr.w * nmu * sg.w);
            *((float4*)(g_h0 + ((size_t)gr * KK + k) * HH + tx * 4)) = m;
        }
    }
}

// ---------------- edge mask: CSR-row-tiled, ALL K experts in one pass ----------------
// grid NN/16. Group handles one dst row for all 4 experts; per edge: 4 independent
// A[src] loads; ewc + out_em written as single STG.128s.
__global__ __launch_bounds__(256) void edge_mask_kernel(
    const float* __restrict__ emb1, const float* __restrict__ emW2,
    const float* __restrict__ emb2, float* __restrict__ out_em)
{
    __shared__ __align__(16) float b1s[4][64];
    __shared__ __align__(16) float w2s[4][64];
    int tid = threadIdx.x;
    {
        int kk = tid >> 6, j = tid & 63;
        b1s[kk][j] = emb1[kk * 64 + j];
        w2s[kk][j] = emW2[kk * 64 + j];
    }
    __syncthreads();
    int lane = tid & 15, grp = tid >> 4;
    int gr = blockIdx.x * 16 + grp;        // NN % 16 == 0

    float4 bb[4], w[4];
    float b2v[4];
    #pragma unroll
    for (int k = 0; k < 4; k++) {
        const float* ABk = g_AB + (size_t)k * NN * 128;
        float4 b = *((const float4*)(ABk + (size_t)gr * 128 + 64) + lane);
        float4 bi = ((const float4*)b1s[k])[lane];
        bb[k] = make_float4(b.x + bi.x, b.y + bi.y, b.z + bi.z, b.w + bi.w);
        w[k] = ((const float4*)w2s[k])[lane];
        b2v[k] = emb2[k];
    }

    int beg = g_off[gr], end = g_off[gr + 1];
    for (int p = beg; p < end; p++) {
        int s = g_csr_src[p];
        float pp[4];
        #pragma unroll
        for (int k = 0; k < 4; k++) {
            const float* ABk = g_AB + (size_t)k * NN * 128;
            float4 a = *((const float4*)(ABk + (size_t)s * 128) + lane);
            pp[k] = fmaxf(a.x + bb[k].x, 0.f) * w[k].x
                  + fmaxf(a.y + bb[k].y, 0.f) * w[k].y
                  + fmaxf(a.z + bb[k].z, 0.f) * w[k].z
                  + fmaxf(a.w + bb[k].w, 0.f) * w[k].w;
        }
        #pragma unroll
        for (int off = 8; off > 0; off >>= 1) {
            pp[0] += __shfl_down_sync(0xffffffffu, pp[0], off, 16);
            pp[1] += __shfl_down_sync(0xffffffffu, pp[1], off, 16);
            pp[2] += __shfl_down_sync(0xffffffffu, pp[2], off, 16);
            pp[3] += __shfl_down_sync(0xffffffffu, pp[3], off, 16);
        }
        if (lane == 0) {
            float4 sg;
            sg.x = sigmoidf_(pp[0] + b2v[0]);
            sg.y = sigmoidf_(pp[1] + b2v[1]);
            sg.z = sigmoidf_(pp[2] + b2v[2]);
            sg.w = sigmoidf_(pp[3] + b2v[3]);
            *((float4*)(g_ewc + (size_t)p * 4)) = sg;
            *((float4*)(out_em + (size_t)g_csr_eid[p] * 4)) = sg;
        }
    }
}

// ---------------- finalize ----------------
__global__ __launch_bounds__(64) void finalize_kernel(
    const float* __restrict__ clfW, const float* __restrict__ clfb,
    float* __restrict__ out_logits, float* __restrict__ out_hstab,
    float* __restrict__ out_horig)
{
    int b = blockIdx.x, t = threadIdx.x;
    __shared__ float hs[64];
    float inv = 1.0f / fmaxf((float)g_cnt[b], 1.0f);
    out_horig[b * HH + t] = g_poolZ[b * HH + t] * inv;
    for (int k = 0; k < KK; k++) {
        float v = g_poolS[((size_t)k * NB_BATCH + b) * HH + t] * inv;
        out_hstab[((size_t)b * KK + k) * HH + t] = v;
        hs[t] = v;
        __syncthreads();
        if (t < CC) {
            float sacc = clfb[k * CC + t];
            #pragma unroll 8
            for (int h2 = 0; h2 < HH; h2++)
                sacc += hs[h2] * clfW[((size_t)k * HH + h2) * CC + t];
            out_logits[((size_t)b * KK + k) * CC + t] = sacc;
        }
        __syncthreads();
    }
}

// ---------------- host launch ----------------
extern "C" void kernel_launch(void* const* d_in, const int* in_sizes, int n_in,
                              void* d_out, int out_size)
{
    const float* x     = (const float*)d_in[0];
    const int*   ei    = (const int*)d_in[1];
    const int*   batch = (const int*)d_in[2];
    const float* ceW1  = (const float*)d_in[3];
    const float* ceb1  = (const float*)d_in[4];
    const float* ceW2  = (const float*)d_in[5];
    const float* ceb2  = (const float*)d_in[6];
    const float* ceeps = (const float*)d_in[7];
    const float* clW1  = (const float*)d_in[8];
    const float* clb1  = (const float*)d_in[9];
    const float* clW2  = (const float*)d_in[10];
    const float* clb2  = (const float*)d_in[11];
    const float* cleps = (const float*)d_in[12];
    const float* nmW1  = (const float*)d_in[13];
    const float* nmb1  = (const float*)d_in[14];
    const float* nmW2  = (const float*)d_in[15];
    const float* nmb2  = (const float*)d_in[16];
    const float* emW1  = (const float*)d_in[17];
    const float* emb1  = (const float*)d_in[18];
    const float* emW2  = (const float*)d_in[19];
    const float* emb2  = (const float*)d_in[20];
    const float* fmW1  = (const float*)d_in[21];
    const float* fmb1  = (const float*)d_in[22];
    const float* fmW2  = (const float*)d_in[23];
    const float* fmb2  = (const float*)d_in[24];
    const float* clfW  = (const float*)d_in[25];
    const float* clfb  = (const float*)d_in[26];

    const int* src = ei;
    const int* dst = ei + EE;

    float* Z_p;     cudaGetSymbolAddress((void**)&Z_p, g_Z);
    float* h0_p;    cudaGetSymbolAddress((void**)&h0_p, g_h0);
    float* h1_p;    cudaGetSymbolAddress((void**)&h1_p, g_h1);
    float* poolZ_p; cudaGetSymbolAddress((void**)&poolZ_p, g_poolZ);
    float* poolS_p; cudaGetSymbolAddress((void**)&poolS_p, g_poolS);

    float* out        = (float*)d_out;
    float* out_logits = out;
    float* out_hstab  = out_logits + NB_BATCH * KK * CC;
    float* out_horig  = out_hstab + NB_BATCH * KK * HH;
    float* out_nm     = out_horig + NB_BATCH * HH;
    float* out_em     = out_nm + (size_t)NN * KK;
    float* out_fm     = out_em + (size_t)EE * KK;

    const int GB = (NN + 63) / 64;          // 782
    const int GC = NN / 16;                 // 3125
    const int EG = (EE + 255) / 256;        // 3125
    const int EM_GRID = NN / 16;            // 3125
    const int IG = (KK * NB_BATCH * HH + 255) / 256;

    // ---- CSR build + init ----
    init_kernel<<<IG, 256>>>();
    histcnt_kernel<<<EG, 256>>>(dst, batch);
    scan_kernel<<<1, 1024>>>();
    fill_kernel<<<EG, 256>>>(src, dst);

    // ---- causal encoder GIN (3 layers); layer 3 fuses Z pooling ----
    ginenc_kernel<<<GB, 256>>>(x, h1_p, ceeps, 0, ceW1, ceb1, ceW2, ceb2, nullptr, nullptr);
    ginenc_kernel<<<GB, 256>>>(h1_p, h0_p, ceeps, 1, ceW1 + 4096, ceb1 + 64,
                               ceW2 + 4096, ceb2 + 64, nullptr, nullptr);
    ginenc_kernel<<<GB, 256>>>(h0_p, Z_p, ceeps, 2, ceW1 + 8192, ceb1 + 128,
                               ceW2 + 8192, ceb2 + 128, poolZ_p, batch);

    // ---- masks (writes interleaved g_h0) ----
    mask_kernel<<<dim3(GB, KK), 256>>>(Z_p, x, nmW1, nmb1, nmW2, nmb2,
                                       emW1, fmW1, fmb1, fmW2, fmb2,
                                       out_nm, out_fm);
    edge_mask_kernel<<<EM_GRID, 256>>>(emb1, emW2, emb2, out_em);

    // ---- classifier GIN (3 layers, all K); layer 3 fuses pooling ----
    gincl_kernel<<<GC, 256>>>(h0_p, h1_p, cleps, 0, clW1, clb1, clW2, clb2,
                              nullptr, nullptr);
    gincl_kernel<<<GC, 256>>>(h1_p, h0_p, cleps, 1, clW1 + 4096, clb1 + 64,
                              clW2 + 4096, clb2 + 64, nullptr, nullptr);
    gincl_kernel<<<GC, 256>>>(h0_p, h1_p, cleps, 2, clW1 + 8192, clb1 + 128,
                              clW2 + 8192, clb2 + 128, poolS_p, batch);

    // ---- finalize ----
    finalize_kernel<<<NB_BATCH, 64>>>(clfW, clfb, out_logits, out_hstab, out_horig);
}

// round 15
// speedup vs baseline: 1.2124x; 1.0059x over previous
#include <cuda_runtime.h>
#include <math.h>
#include <stdint.h>

#define NN 50000
#define EE 800000
#define HH 64
#define FF 64
#define CC 10
#define KK 4
#define LL 3
#define NB_BATCH 256
#define SPAD 68
#define WSPAD 72

// ---------------- device scratch ----------------
__device__ float g_Z[NN * HH];
__device__ float g_h0[(size_t)NN * KK * HH];
__device__ float g_h1[(size_t)NN * KK * HH];
__device__ float g_AB[(size_t)KK * NN * 128];
__device__ float g_ewc[(size_t)EE * KK];
__device__ int   g_deg[NN];
__device__ int   g_off[NN + 1];
__device__ int   g_fill[NN];
__device__ int   g_csr_src[EE + 4];
__device__ int   g_csr_eid[EE];
__device__ float g_poolZ[NB_BATCH * HH];
__device__ float g_poolS[KK * NB_BATCH * HH];
__device__ int   g_cnt[NB_BATCH];

__device__ __forceinline__ void red_add_f2(float* p, float a, float b) {
    asm volatile("red.global.add.v2.f32 [%0], {%1,%2};"
                 :: "l"(p), "f"(a), "f"(b) : "memory");
}
__device__ __forceinline__ float sigmoidf_(float v) { return 1.0f / (1.0f + expf(-v)); }

__device__ __forceinline__ uint32_t tf32_rna(float a) {
    uint32_t h; asm("cvt.rna.tf32.f32 %0, %1;" : "=r"(h) : "f"(a)); return h;
}

__device__ __forceinline__ void loadWsplit(const float* __restrict__ W,
                                           float* Wh, float* Wl, int tid) {
    for (int i = tid; i < 1024; i += 256) {
        float4 w = ((const float4*)W)[i];
        int k = i >> 4, j = (i & 15) * 4;
        float4 h, l;
        h.x = __uint_as_float(tf32_rna(w.x)); l.x = __uint_as_float(tf32_rna(w.x - h.x));
        h.y = __uint_as_float(tf32_rna(w.y)); l.y = __uint_as_float(tf32_rna(w.y - h.y));
        h.z = __uint_as_float(tf32_rna(w.z)); l.z = __uint_as_float(tf32_rna(w.z - h.z));
        h.w = __uint_as_float(tf32_rna(w.w)); l.w = __uint_as_float(tf32_rna(w.w - h.w));
        *((float4*)&Wh[k * WSPAD + j]) = h;
        *((float4*)&Wl[k * WSPAD + j]) = l;
    }
}

#define MMA_TF32(c, A0, A1, A2, A3, B0, B1) \
    asm("mma.sync.aligned.m16n8k8.row.col.f32.tf32.tf32.f32 " \
        "{%0,%1,%2,%3}, {%4,%5,%6,%7}, {%8,%9}, {%0,%1,%2,%3};" \
        : "+f"((c)[0]), "+f"((c)[1]), "+f"((c)[2]), "+f"((c)[3]) \
        : "r"(A0), "r"(A1), "r"(A2), "r"(A3), "r"(B0), "r"(B1))

__device__ __forceinline__ void gemm_frag(const float* As, const float* Wh,
                                          const float* Wl, float c[4][4],
                                          int lane, int warp) {
    int mband = (warp & 3) * 16, nhalf = (warp >> 2) * 32;
    int lr = lane >> 2, lc = lane & 3;
    #pragma unroll
    for (int nt = 0; nt < 4; nt++)
        #pragma unroll
        for (int q = 0; q < 4; q++) c[nt][q] = 0.f;
    #pragma unroll
    for (int ks = 0; ks < 8; ks++) {
        int k0 = ks * 8;
        float a0 = As[(mband + lr) * SPAD + k0 + lc];
        float a1 = As[(mband + 8 + lr) * SPAD + k0 + lc];
        float a2 = As[(mband + lr) * SPAD + k0 + 4 + lc];
        float a3 = As[(mband + 8 + lr) * SPAD + k0 + 4 + lc];
        uint32_t ah0 = tf32_rna(a0), ah1 = tf32_rna(a1);
        uint32_t ah2 = tf32_rna(a2), ah3 = tf32_rna(a3);
        uint32_t al0 = tf32_rna(a0 - __uint_as_float(ah0));
        uint32_t al1 = tf32_rna(a1 - __uint_as_float(ah1));
        uint32_t al2 = tf32_rna(a2 - __uint_as_float(ah2));
        uint32_t al3 = tf32_rna(a3 - __uint_as_float(ah3));
        #pragma unroll
        for (int nt = 0; nt < 4; nt++) {
            int n = nhalf + nt * 8 + lr;
            uint32_t bh0 = __float_as_uint(Wh[(k0 + lc) * WSPAD + n]);
            uint32_t bl0 = __float_as_uint(Wl[(k0 + lc) * WSPAD + n]);
            uint32_t bh1 = __float_as_uint(Wh[(k0 + 4 + lc) * WSPAD + n]);
            uint32_t bl1 = __float_as_uint(Wl[(k0 + 4 + lc) * WSPAD + n]);
            MMA_TF32(c[nt], ah0, ah1, ah2, ah3, bh0, bh1);
            MMA_TF32(c[nt], al0, al1, al2, al3, bh0, bh1);
            MMA_TF32(c[nt], ah0, ah1, ah2, ah3, bl0, bl1);
        }
    }
}

__device__ __forceinline__ void stage_frag(const float c[4][4], float* Cs,
                                           int lane, int warp) {
    int mband = (warp & 3) * 16, nhalf = (warp >> 2) * 32;
    int lr = lane >> 2, lc = lane & 3;
    #pragma unroll
    for (int nt = 0; nt < 4; nt++) {
        int col = nhalf + nt * 8 + lc * 2;
        *((float2*)&Cs[(mband + lr) * SPAD + col])     = make_float2(c[nt][0], c[nt][1]);
        *((float2*)&Cs[(mband + 8 + lr) * SPAD + col]) = make_float2(c[nt][2], c[nt][3]);
    }
}

__device__ __forceinline__ void read_acc(const float* Cs, float acc[4][4],
                                         int tx, int ty) {
    #pragma unroll
    for (int i = 0; i < 4; i++) {
        float4 v = *((const float4*)&Cs[(ty * 4 + i) * SPAD + tx * 4]);
        acc[i][0] = v.x; acc[i][1] = v.y; acc[i][2] = v.z; acc[i][3] = v.w;
    }
}

__device__ __forceinline__ void frag_relu_to_As(const float c[4][4], const float* bsh,
                                                float* As, int lane, int warp) {
    int mband = (warp & 3) * 16, nhalf = (warp >> 2) * 32;
    int lr = lane >> 2, lc = lane & 3;
    #pragma unroll
    for (int nt = 0; nt < 4; nt++) {
        int col = nhalf + nt * 8 + lc * 2;
        float b0 = bsh[col], b1 = bsh[col + 1];
        *((float2*)&As[(mband + lr) * SPAD + col]) =
            make_float2(fmaxf(c[nt][0] + b0, 0.f), fmaxf(c[nt][1] + b1, 0.f));
        *((float2*)&As[(mband + 8 + lr) * SPAD + col]) =
            make_float2(fmaxf(c[nt][2] + b0, 0.f), fmaxf(c[nt][3] + b1, 0.f));
    }
}

// ---------------- init ----------------
__global__ __launch_bounds__(256) void init_kernel() {
    int i = blockIdx.x * 256 + threadIdx.x;
    if (i < NN) { g_deg[i] = 0; g_fill[i] = 0; }
    if (i < NB_BATCH) g_cnt[i] = 0;
    if (i < NB_BATCH * HH) g_poolZ[i] = 0.f;
    if (i < KK * NB_BATCH * HH) g_poolS[i] = 0.f;
    if (i < 4) g_csr_src[EE + i] = 0;
}

__global__ __launch_bounds__(256) void histcnt_kernel(const int* __restrict__ dst,
                                                      const int* __restrict__ batch) {
    int e = blockIdx.x * 256 + threadIdx.x;
    if (e < EE) atomicAdd(&g_deg[dst[e]], 1);
    if (e < NN) atomicAdd(&g_cnt[batch[e]], 1);
}

__global__ __launch_bounds__(1024) void scan_kernel() {
    __shared__ int wsum[32];
    __shared__ int carry_s;
    int tid = threadIdx.x, lane = tid & 31, wid = tid >> 5;
    if (tid == 0) carry_s = 0;
    __syncthreads();
    for (int base = 0; base < NN; base += 1024) {
        int v = (base + tid < NN) ? g_deg[base + tid] : 0;
        int inc = v;
        #pragma unroll
        for (int off = 1; off < 32; off <<= 1) {
            int t = __shfl_up_sync(0xffffffffu, inc, off);
            if (lane >= off) inc += t;
        }
        if (lane == 31) wsum[wid] = inc;
        __syncthreads();
        if (wid == 0) {
            int s = wsum[lane];
            #pragma unroll
            for (int off = 1; off < 32; off <<= 1) {
                int t = __shfl_up_sync(0xffffffffu, s, off);
                if (lane >= off) s += t;
            }
            wsum[lane] = s;
        }
        __syncthreads();
        int wpre = wid ? wsum[wid - 1] : 0;
        int excl = carry_s + wpre + inc - v;
        if (base + tid < NN) g_off[base + tid] = excl;
        __syncthreads();
        if (tid == 0) carry_s += wsum[31];
        __syncthreads();
    }
    if (threadIdx.x == 0) g_off[NN] = carry_s;
}

__global__ __launch_bounds__(256) void fill_kernel(const int* __restrict__ src,
                                                   const int* __restrict__ dst) {
    int e = blockIdx.x * 256 + threadIdx.x;
    if (e < EE) {
        int d = dst[e];
        int pos = g_off[d] + atomicAdd(&g_fill[d], 1);
        g_csr_src[pos] = src[e];
        g_csr_eid[pos] = e;
    }
}

// ---------------- encoder GIN layer ----------------
__global__ __launch_bounds__(256) void ginenc_kernel(
    const float* __restrict__ hin, float* __restrict__ hout,
    const float* __restrict__ eps_ptr, int lidx,
    const float* __restrict__ W1, const float* __restrict__ b1,
    const float* __restrict__ W2, const float* __restrict__ b2,
    float* __restrict__ pool, const int* __restrict__ batch)
{
    __shared__ __align__(16) float As[64 * SPAD];
    __shared__ __align__(16) float Wh[64 * WSPAD];
    __shared__ __align__(16) float Wl[64 * WSPAD];
    __shared__ float bsh[64], bsh2[64];
    int tid = threadIdx.x;
    int r0 = blockIdx.x * 64;
    float epsv = 1.0f + eps_ptr[lidx];
    int part = tid & 15, grp = tid >> 4;
    int lane = tid & 31, warp = tid >> 5;

    #pragma unroll
    for (int rr = 0; rr < 4; rr++) {
        int row = rr * 16 + grp;
        int gr = r0 + row;
        float4 a = make_float4(0.f, 0.f, 0.f, 0.f);
        if (gr < NN) {
            float4 h = ((const float4*)(hin + (size_t)gr * HH))[part];
            a.x = epsv * h.x; a.y = epsv * h.y; a.z = epsv * h.z; a.w = epsv * h.w;
            int beg = g_off[gr], end = g_off[gr + 1];
            int p = beg;
            int sA = g_csr_src[p], sB = g_csr_src[p + 1];
            for (; p + 1 < end; p += 2) {
                int s0 = sA, s1 = sB;
                sA = g_csr_src[p + 2]; sB = g_csr_src[p + 3];
                float4 v0 = ((const float4*)(hin + (size_t)s0 * HH))[part];
                float4 v1 = ((const float4*)(hin + (size_t)s1 * HH))[part];
                a.x += v0.x + v1.x; a.y += v0.y + v1.y;
                a.z += v0.z + v1.z; a.w += v0.w + v1.w;
            }
            if (p < end) {
                float4 v0 = ((const float4*)(hin + (size_t)sA * HH))[part];
                a.x += v0.x; a.y += v0.y; a.z += v0.z; a.w += v0.w;
            }
        }
        *((float4*)&As[row * SPAD + part * 4]) = a;
    }

    loadWsplit(W1, Wh, Wl, tid);
    if (tid < 64) { bsh[tid] = b1[tid]; bsh2[tid] = b2[tid]; }
    __syncthreads();

    float c[4][4];
    gemm_frag(As, Wh, Wl, c, lane, warp);
    __syncthreads();
    frag_relu_to_As(c, bsh, As, lane, warp);
    loadWsplit(W2, Wh, Wl, tid);
    __syncthreads();
    gemm_frag(As, Wh, Wl, c, lane, warp);

    // fragment-direct final epilogue
    {
        int mband = (warp & 3) * 16, nhalf = (warp >> 2) * 32;
        int lr = lane >> 2, lc = lane & 3;
        int ga = r0 + mband + lr, gb = r0 + mband + 8 + lr;
        int bA = 0, bB = 0;
        if (pool) {
            if (ga < NN) bA = batch[ga];
            if (gb < NN) bB = batch[gb];
        }
        #pragma unroll
        for (int nt = 0; nt < 4; nt++) {
            int col = nhalf + nt * 8 + lc * 2;
            float b0 = bsh2[col], b1v = bsh2[col + 1];
            if (ga < NN) {
                float ox = fmaxf(c[nt][0] + b0, 0.f), oy = fmaxf(c[nt][1] + b1v, 0.f);
                *((float2*)(hout + (size_t)ga * HH + col)) = make_float2(ox, oy);
                if (pool) red_add_f2(pool + (size_t)bA * HH + col, ox, oy);
            }
            if (gb < NN) {
                float ox = fmaxf(c[nt][2] + b0, 0.f), oy = fmaxf(c[nt][3] + b1v, 0.f);
                *((float2*)(hout + (size_t)gb * HH + col)) = make_float2(ox, oy);
                if (pool) red_add_f2(pool + (size_t)bB * HH + col, ox, oy);
            }
        }
    }
}

// ---------------- classifier GIN layer, all K experts, interleaved [n][k][64] ----------
__global__ __launch_bounds__(256) void gincl_kernel(
    const float* __restrict__ hin, float* __restrict__ hout,
    const float* __restrict__ eps_ptr, int lidx,
    const float* __restrict__ W1, const float* __restrict__ b1,
    const float* __restrict__ W2, const float* __restrict__ b2,
    float* __restrict__ pool, const int* __restrict__ batch)
{
    __shared__ __align__(16) float As[64 * SPAD];
    __shared__ __align__(16) float Wh[64 * WSPAD];
    __shared__ __align__(16) float Wl[64 * WSPAD];
    __shared__ float bsh[64], bsh2[64];
    int tid = threadIdx.x;
    int n0 = blockIdx.x * 16;
    float epsv = 1.0f + eps_ptr[lidx];
    int part = tid & 15, grp = tid >> 4;
    int lane = tid & 31, warp = tid >> 5;

    {
        int gr = n0 + grp;
        const float4* hbase = (const float4*)(hin + (size_t)gr * KK * HH);
        float4 a[4];
        #pragma unroll
        for (int k = 0; k < 4; k++) {
            float4 h = hbase[k * 16 + part];
            a[k].x = epsv * h.x; a[k].y = epsv * h.y;
            a[k].z = epsv * h.z; a[k].w = epsv * h.w;
        }
        int beg = g_off[gr], end = g_off[gr + 1];
        int p = beg;
        int sA = g_csr_src[p], sB = g_csr_src[p + 1];
        for (; p + 1 < end; p += 2) {
            int s0 = sA, s1 = sB;
            sA = g_csr_src[p + 2]; sB = g_csr_src[p + 3];
            float4 w0 = *((const float4*)(g_ewc + (size_t)p * 4));
            float4 w1 = *((const float4*)(g_ewc + (size_t)(p + 1) * 4));
            const float4* vb0 = (const float4*)(hin + (size_t)s0 * KK * HH);
            const float4* vb1 = (const float4*)(hin + (size_t)s1 * KK * HH);
            float4 v0 = vb0[0 * 16 + part];
            float4 v1 = vb0[1 * 16 + part];
            float4 v2 = vb0[2 * 16 + part];
            float4 v3 = vb0[3 * 16 + part];
            float4 u0 = vb1[0 * 16 + part];
            float4 u1 = vb1[1 * 16 + part];
            float4 u2 = vb1[2 * 16 + part];
            float4 u3 = vb1[3 * 16 + part];
            a[0].x = fmaf(w0.x, v0.x, a[0].x); a[0].y = fmaf(w0.x, v0.y, a[0].y);
            a[0].z = fmaf(w0.x, v0.z, a[0].z); a[0].w = fmaf(w0.x, v0.w, a[0].w);
            a[1].x = fmaf(w0.y, v1.x, a[1].x); a[1].y = fmaf(w0.y, v1.y, a[1].y);
            a[1].z = fmaf(w0.y, v1.z, a[1].z); a[1].w = fmaf(w0.y, v1.w, a[1].w);
            a[2].x = fmaf(w0.z, v2.x, a[2].x); a[2].y = fmaf(w0.z, v2.y, a[2].y);
            a[2].z = fmaf(w0.z, v2.z, a[2].z); a[2].w = fmaf(w0.z, v2.w, a[2].w);
            a[3].x = fmaf(w0.w, v3.x, a[3].x); a[3].y = fmaf(w0.w, v3.y, a[3].y);
            a[3].z = fmaf(w0.w, v3.z, a[3].z); a[3].w = fmaf(w0.w, v3.w, a[3].w);
            a[0].x = fmaf(w1.x, u0.x, a[0].x); a[0].y = fmaf(w1.x, u0.y, a[0].y);
            a[0].z = fmaf(w1.x, u0.z, a[0].z); a[0].w = fmaf(w1.x, u0.w, a[0].w);
            a[1].x = fmaf(w1.y, u1.x, a[1].x); a[1].y = fmaf(w1.y, u1.y, a[1].y);
            a[1].z = fmaf(w1.y, u1.z, a[1].z); a[1].w = fmaf(w1.y, u1.w, a[1].w);
            a[2].x = fmaf(w1.z, u2.x, a[2].x); a[2].y = fmaf(w1.z, u2.y, a[2].y);
            a[2].z = fmaf(w1.z, u2.z, a[2].z); a[2].w = fmaf(w1.z, u2.w, a[2].w);
            a[3].x = fmaf(w1.w, u3.x, a[3].x); a[3].y = fmaf(w1.w, u3.y, a[3].y);
            a[3].z = fmaf(w1.w, u3.z, a[3].z); a[3].w = fmaf(w1.w, u3.w, a[3].w);
        }
        if (p < end) {
            float4 w0 = *((const float4*)(g_ewc + (size_t)p * 4));
            const float4* vb = (const float4*)(hin + (size_t)sA * KK * HH);
            float4 v0 = vb[0 * 16 + part];
            float4 v1 = vb[1 * 16 + part];
            float4 v2 = vb[2 * 16 + part];
            float4 v3 = vb[3 * 16 + part];
            a[0].x = fmaf(w0.x, v0.x, a[0].x); a[0].y = fmaf(w0.x, v0.y, a[0].y);
            a[0].z = fmaf(w0.x, v0.z, a[0].z); a[0].w = fmaf(w0.x, v0.w, a[0].w);
            a[1].x = fmaf(w0.y, v1.x, a[1].x); a[1].y = fmaf(w0.y, v1.y, a[1].y);
            a[1].z = fmaf(w0.y, v1.z, a[1].z); a[1].w = fmaf(w0.y, v1.w, a[1].w);
            a[2].x = fmaf(w0.z, v2.x, a[2].x); a[2].y = fmaf(w0.z, v2.y, a[2].y);
            a[2].z = fmaf(w0.z, v2.z, a[2].z); a[2].w = fmaf(w0.z, v2.w, a[2].w);
            a[3].x = fmaf(w0.w, v3.x, a[3].x); a[3].y = fmaf(w0.w, v3.y, a[3].y);
            a[3].z = fmaf(w0.w, v3.z, a[3].z); a[3].w = fmaf(w0.w, v3.w, a[3].w);
        }
        #pragma unroll
        for (int k = 0; k < 4; k++)
            *((float4*)&As[(grp * 4 + k) * SPAD + part * 4]) = a[k];
    }

    loadWsplit(W1, Wh, Wl, tid);
    if (tid < 64) { bsh[tid] = b1[tid]; bsh2[tid] = b2[tid]; }
    __syncthreads();

    float c[4][4];
    gemm_frag(As, Wh, Wl, c, lane, warp);
    __syncthreads();
    frag_relu_to_As(c, bsh, As, lane, warp);
    loadWsplit(W2, Wh, Wl, tid);
    __syncthreads();
    gemm_frag(As, Wh, Wl, c, lane, warp);

    // fragment-direct final epilogue (row = node*4 + expert)
    {
        int mband = (warp & 3) * 16, nhalf = (warp >> 2) * 32;
        int lr = lane >> 2, lc = lane & 3;
        int ra = mband + lr, rb = mband + 8 + lr;
        int gna = n0 + (ra >> 2), kea = ra & 3;
        int gnb = n0 + (rb >> 2), keb = rb & 3;
        int bA = 0, bB = 0;
        if (pool) { bA = batch[gna]; bB = batch[gnb]; }
        float* ha = hout + ((size_t)gna * KK + kea) * HH;
        float* hb = hout + ((size_t)gnb * KK + keb) * HH;
        #pragma unroll
        for (int nt = 0; nt < 4; nt++) {
            int col = nhalf + nt * 8 + lc * 2;
            float b0 = bsh2[col], b1v = bsh2[col + 1];
            float ox = fmaxf(c[nt][0] + b0, 0.f), oy = fmaxf(c[nt][1] + b1v, 0.f);
            *((float2*)(ha + col)) = make_float2(ox, oy);
            if (pool) red_add_f2(pool + ((size_t)kea * NB_BATCH + bA) * HH + col, ox, oy);
            float px = fmaxf(c[nt][2] + b0, 0.f), py = fmaxf(c[nt][3] + b1v, 0.f);
            *((float2*)(hb + col)) = make_float2(px, py);
            if (pool) red_add_f2(pool + ((size_t)keb * NB_BATCH + bB) * HH + col, px, py);
        }
    }
}

// ---------------- fused mask kernel ----------------
__global__ __launch_bounds__(256) void mask_kernel(
    const float* __restrict__ Z, const float* __restrict__ x,
    const float* __restrict__ nmW1, const float* __restrict__ nmb1,
    const float* __restrict__ nmW2, const float* __restrict__ nmb2,
    const float* __restrict__ emW1,
    const float* __restrict__ fmW1, const float* __restrict__ fmb1,
    const float* __restrict__ fmW2, const float* __restrict__ fmb2,
    float* __restrict__ out_nm, float* __restrict__ out_fm)
{
    __shared__ __align__(16) float As[64 * SPAD];
    __shared__ __align__(16) float Wh[64 * WSPAD];
    __shared__ __align__(16) float Wl[64 * WSPAD];
    __shared__ float bsh[64], bsh2[64], w2s[64], nmv[64];
    int tid = threadIdx.x, r0 = blockIdx.x * 64;
    int k = blockIdx.y;
    int lane = tid & 31, warp = tid >> 5;
    int mband = (warp & 3) * 16, nhalf = (warp >> 2) * 32;
    int lr = lane >> 2, lc = lane & 3;
    const float* nmW1k = nmW1 + (size_t)k * 4096;
    const float* nmb1k = nmb1 + (size_t)k * 64;
    const float* nmW2k = nmW2 + (size_t)k * 64;
    const float* emW1k = emW1 + (size_t)k * 8192;
    const float* fmW1k = fmW1 + (size_t)k * 4096;
    const float* fmb1k = fmb1 + (size_t)k * 64;
    const float* fmW2k = fmW2 + (size_t)k * 4096;
    const float* fmb2k = fmb2 + (size_t)k * 64;
    float* ABk = g_AB + (size_t)k * NN * 128;

    {
        int row = tid >> 2, p0 = (tid & 3) * 4, gr = r0 + row;
        #pragma unroll
        for (int q = 0; q < 4; q++) {
            float4 v = make_float4(0.f, 0.f, 0.f, 0.f);
            if (gr < NN) v = ((const float4*)(Z + (size_t)gr * HH))[p0 + q];
            *((float4*)&As[row * SPAD + (p0 + q) * 4]) = v;
        }
    }
    int tx = tid & 15, ty = tid >> 4;
    float c[4][4], acc[4][4];
    int ga = r0 + mband + lr, gb = r0 + mband + 8 + lr;

    // ---- node mask (needs cross-warp reduce -> staged) ----
    loadWsplit(nmW1k, Wh, Wl, tid);
    if (tid < 64) { bsh[tid] = nmb1k[tid]; w2s[tid] = nmW2k[tid]; }
    __syncthreads();
    gemm_frag(As, Wh, Wl, c, lane, warp);
    __syncthreads();
    stage_frag(c, Wh, lane, warp);
    __syncthreads();
    read_acc(Wh, acc, tx, ty);
    float b2v = nmb2[k];
    #pragma unroll
    for (int i = 0; i < 4; i++) {
        float p = 0.f;
        #pragma unroll
        for (int j = 0; j < 4; j++)
            p += fmaxf(acc[i][j] + bsh[tx*4+j], 0.f) * w2s[tx*4+j];
        #pragma unroll
        for (int off = 8; off > 0; off >>= 1)
            p += __shfl_down_sync(0xffffffffu, p, off, 16);
        if (tx == 0) {
            float sg = sigmoidf_(p + b2v);
            nmv[ty * 4 + i] = sg;
            int gr = r0 + ty * 4 + i;
            if (gr < NN) out_nm[(size_t)gr * KK + k] = sg;
        }
    }
    __syncthreads();

    // ---- AB precompute (fragment-direct to global) ----
    #pragma unroll
    for (int half = 0; half < 2; half++) {
        loadWsplit(emW1k + half * 4096, Wh, Wl, tid);
        __syncthreads();
        gemm_frag(As, Wh, Wl, c, lane, warp);
        #pragma unroll
        for (int nt = 0; nt < 4; nt++) {
            int col = half * 64 + nhalf + nt * 8 + lc * 2;
            if (ga < NN)
                *((float2*)(ABk + (size_t)ga * 128 + col)) = make_float2(c[nt][0], c[nt][1]);
            if (gb < NN)
                *((float2*)(ABk + (size_t)gb * 128 + col)) = make_float2(c[nt][2], c[nt][3]);
        }
        __syncthreads();
    }

    // ---- feature mask + masked_x ----
    loadWsplit(fmW1k, Wh, Wl, tid);
    if (tid < 64) { bsh[tid] = fmb1k[tid]; bsh2[tid] = fmb2k[tid]; }
    __syncthreads();
    gemm_frag(As, Wh, Wl, c, lane, warp);
    __syncthreads();
    frag_relu_to_As(c, bsh, As, lane, warp);
    loadWsplit(fmW2k, Wh, Wl, tid);
    __syncthreads();
    gemm_frag(As, Wh, Wl, c, lane, warp);

    // fragment-direct fm epilogue
    {
        float nmu_a = (ga < NN) ? nmv[mband + lr] : 0.f;
        float nmu_b = (gb < NN) ? nmv[mband + 8 + lr] : 0.f;
        #pragma unroll
        for (int nt = 0; nt < 4; nt++) {
            int col = nhalf + nt * 8 + lc * 2;
            float b0 = bsh2[col], b1v = bsh2[col + 1];
            if (ga < NN) {
                float2 xr = *((const float2*)(x + (size_t)ga * FF + col));
                float sx = sigmoidf_(c[nt][0] + b0), sy = sigmoidf_(c[nt][1] + b1v);
                *((float2*)(out_fm + ((size_t)ga * KK + k) * FF + col)) = make_float2(sx, sy);
                *((float2*)(g_h0 + ((size_t)ga * KK + k) * HH + col)) =
                    make_float2(xr.x * nmu_a * sx, xr.y * nmu_a * sy);
            }
            if (gb < NN) {
                float2 xr = *((const float2*)(x + (size_t)gb * FF + col));
                float sx = sigmoidf_(c[nt][2] + b0), sy = sigmoidf_(c[nt][3] + b1v);
                *((float2*)(out_fm + ((size_t)gb * KK + k) * FF + col)) = make_float2(sx, sy);
                *((float2*)(g_h0 + ((size_t)gb * KK + k) * HH + col)) =
                    make_float2(xr.x * nmu_b * sx, xr.y * nmu_b * sy);
            }
        }
    }
}

// ---------------- edge mask: CSR-row-tiled, ALL K experts in one pass ----------------
__global__ __launch_bounds__(256) void edge_mask_kernel(
    const float* __restrict__ emb1, const float* __restrict__ emW2,
    const float* __restrict__ emb2, float* __restrict__ out_em)
{
    __shared__ __align__(16) float b1s[4][64];
    __shared__ __align__(16) float w2s[4][64];
    int tid = threadIdx.x;
    {
        int kk = tid >> 6, j = tid & 63;
        b1s[kk][j] = emb1[kk * 64 + j];
        w2s[kk][j] = emW2[kk * 64 + j];
    }
    __syncthreads();
    int lane = tid & 15, grp = tid >> 4;
    int gr = blockIdx.x * 16 + grp;

    float4 bb[4], w[4];
    float b2v[4];
    #pragma unroll
    for (int k = 0; k < 4; k++) {
        const float* ABk = g_AB + (size_t)k * NN * 128;
        float4 b = *((const float4*)(ABk + (size_t)gr * 128 + 64) + lane);
        float4 bi = ((const float4*)b1s[k])[lane];
        bb[k] = make_float4(b.x + bi.x, b.y + bi.y, b.z + bi.z, b.w + bi.w);
        w[k] = ((const float4*)w2s[k])[lane];
        b2v[k] = emb2[k];
    }

    int beg = g_off[gr], end = g_off[gr + 1];
    for (int p = beg; p < end; p++) {
        int s = g_csr_src[p];
        float pp[4];
        #pragma unroll
        for (int k = 0; k < 4; k++) {
            const float* ABk = g_AB + (size_t)k * NN * 128;
            float4 a = *((const float4*)(ABk + (size_t)s * 128) + lane);
            pp[k] = fmaxf(a.x + bb[k].x, 0.f) * w[k].x
                  + fmaxf(a.y + bb[k].y, 0.f) * w[k].y
                  + fmaxf(a.z + bb[k].z, 0.f) * w[k].z
                  + fmaxf(a.w + bb[k].w, 0.f) * w[k].w;
        }
        #pragma unroll
        for (int off = 8; off > 0; off >>= 1) {
            pp[0] += __shfl_down_sync(0xffffffffu, pp[0], off, 16);
            pp[1] += __shfl_down_sync(0xffffffffu, pp[1], off, 16);
            pp[2] += __shfl_down_sync(0xffffffffu, pp[2], off, 16);
            pp[3] += __shfl_down_sync(0xffffffffu, pp[3], off, 16);
        }
        if (lane == 0) {
            float4 sg;
            sg.x = sigmoidf_(pp[0] + b2v[0]);
            sg.y = sigmoidf_(pp[1] + b2v[1]);
            sg.z = sigmoidf_(pp[2] + b2v[2]);
            sg.w = sigmoidf_(pp[3] + b2v[3]);
            *((float4*)(g_ewc + (size_t)p * 4)) = sg;
            *((float4*)(out_em + (size_t)g_csr_eid[p] * 4)) = sg;
        }
    }
}

// ---------------- finalize ----------------
__global__ __launch_bounds__(64) void finalize_kernel(
    const float* __restrict__ clfW, const float* __restrict__ clfb,
    float* __restrict__ out_logits, float* __restrict__ out_hstab,
    float* __restrict__ out_horig)
{
    int b = blockIdx.x, t = threadIdx.x;
    __shared__ float hs[64];
    float inv = 1.0f / fmaxf((float)g_cnt[b], 1.0f);
    out_horig[b * HH + t] = g_poolZ[b * HH + t] * inv;
    for (int k = 0; k < KK; k++) {
        float v = g_poolS[((size_t)k * NB_BATCH + b) * HH + t] * inv;
        out_hstab[((size_t)b * KK + k) * HH + t] = v;
        hs[t] = v;
        __syncthreads();
        if (t < CC) {
            float sacc = clfb[k * CC + t];
            #pragma unroll 8
            for (int h2 = 0; h2 < HH; h2++)
                sacc += hs[h2] * clfW[((size_t)k * HH + h2) * CC + t];
            out_logits[((size_t)b * KK + k) * CC + t] = sacc;
        }
        __syncthreads();
    }
}

// ---------------- host launch ----------------
extern "C" void kernel_launch(void* const* d_in, const int* in_sizes, int n_in,
                              void* d_out, int out_size)
{
    const float* x     = (const float*)d_in[0];
    const int*   ei    = (const int*)d_in[1];
    const int*   batch = (const int*)d_in[2];
    const float* ceW1  = (const float*)d_in[3];
    const float* ceb1  = (const float*)d_in[4];
    const float* ceW2  = (const float*)d_in[5];
    const float* ceb2  = (const float*)d_in[6];
    const float* ceeps = (const float*)d_in[7];
    const float* clW1  = (const float*)d_in[8];
    const float* clb1  = (const float*)d_in[9];
    const float* clW2  = (const float*)d_in[10];
    const float* clb2  = (const float*)d_in[11];
    const float* cleps = (const float*)d_in[12];
    const float* nmW1  = (const float*)d_in[13];
    const float* nmb1  = (const float*)d_in[14];
    const float* nmW2  = (const float*)d_in[15];
    const float* nmb2  = (const float*)d_in[16];
    const float* emW1  = (const float*)d_in[17];
    const float* emb1  = (const float*)d_in[18];
    const float* emW2  = (const float*)d_in[19];
    const float* emb2  = (const float*)d_in[20];
    const float* fmW1  = (const float*)d_in[21];
    const float* fmb1  = (const float*)d_in[22];
    const float* fmW2  = (const float*)d_in[23];
    const float* fmb2  = (const float*)d_in[24];
    const float* clfW  = (const float*)d_in[25];
    const float* clfb  = (const float*)d_in[26];

    const int* src = ei;
    const int* dst = ei + EE;

    float* Z_p;     cudaGetSymbolAddress((void**)&Z_p, g_Z);
    float* h0_p;    cudaGetSymbolAddress((void**)&h0_p, g_h0);
    float* h1_p;    cudaGetSymbolAddress((void**)&h1_p, g_h1);
    float* poolZ_p; cudaGetSymbolAddress((void**)&poolZ_p, g_poolZ);
    float* poolS_p; cudaGetSymbolAddress((void**)&poolS_p, g_poolS);

    float* out        = (float*)d_out;
    float* out_logits = out;
    float* out_hstab  = out_logits + NB_BATCH * KK * CC;
    float* out_horig  = out_hstab + NB_BATCH * KK * HH;
    float* out_nm     = out_horig + NB_BATCH * HH;
    float* out_em     = out_nm + (size_t)NN * KK;
    float* out_fm     = out_em + (size_t)EE * KK;

    const int GB = (NN + 63) / 64;          // 782
    const int GC = NN / 16;                 // 3125
    const int EG = (EE + 255) / 256;        // 3125
    const int EM_GRID = NN / 16;            // 3125
    const int IG = (KK * NB_BATCH * HH + 255) / 256;

    // ---- CSR build + init ----
    init_kernel<<<IG, 256>>>();
    histcnt_kernel<<<EG, 256>>>(dst, batch);
    scan_kernel<<<1, 1024>>>();
    fill_kernel<<<EG, 256>>>(src, dst);

    // ---- causal encoder GIN (3 layers); layer 3 fuses Z pooling ----
    ginenc_kernel<<<GB, 256>>>(x, h1_p, ceeps, 0, ceW1, ceb1, ceW2, ceb2, nullptr, nullptr);
    ginenc_kernel<<<GB, 256>>>(h1_p, h0_p, ceeps, 1, ceW1 + 4096, ceb1 + 64,
                               ceW2 + 4096, ceb2 + 64, nullptr, nullptr);
    ginenc_kernel<<<GB, 256>>>(h0_p, Z_p, ceeps, 2, ceW1 + 8192, ceb1 + 128,
                               ceW2 + 8192, ceb2 + 128, poolZ_p, batch);

    // ---- masks (writes interleaved g_h0) ----
    mask_kernel<<<dim3(GB, KK), 256>>>(Z_p, x, nmW1, nmb1, nmW2, nmb2,
                                       emW1, fmW1, fmb1, fmW2, fmb2,
                                       out_nm, out_fm);
    edge_mask_kernel<<<EM_GRID, 256>>>(emb1, emW2, emb2, out_em);

    // ---- classifier GIN (3 layers, all K); layer 3 fuses pooling ----
    gincl_kernel<<<GC, 256>>>(h0_p, h1_p, cleps, 0, clW1, clb1, clW2, clb2,
                              nullptr, nullptr);
    gincl_kernel<<<GC, 256>>>(h1_p, h0_p, cleps, 1, clW1 + 4096, clb1 + 64,
                              clW2 + 4096, clb2 + 64, nullptr, nullptr);
    gincl_kernel<<<GC, 256>>>(h0_p, h1_p, cleps, 2, clW1 + 8192, clb1 + 128,
                              clW2 + 8192, clb2 + 128, poolS_p, batch);

    // ---- finalize ----
    finalize_kernel<<<NB_BATCH, 64>>>(clfW, clfb, out_logits, out_hstab, out_horig);
}